// round 3
// baseline (speedup 1.0000x reference)
#include <cuda_runtime.h>
#include <cuda_bf16.h>
#include <cstdint>

typedef unsigned long long ull;

#define MUL 16
#define HIDDEN 64
#define TILE_E 128
#define THREADS 256
#define H_STR 66     // padded stride for h rows (bank-conflict-free for even edge ids)
#define S_STR 17     // padded stride for s rows

#define INV_SQRT8 0.35355339059327373f
#define INV_SQRT3 0.5773502691896258f
// PATH_ALPHA/sqrt(HIDDEN) = (1/sqrt(32)) * (1/8)
#define SCALE_OUT 0.022097086912079608f
#define INV_SQRT_MUL 0.25f

// ---------- f32x2 packed helpers (Blackwell) ----------
__device__ __forceinline__ ull pack2(float lo, float hi) {
    ull r;
    asm("mov.b64 %0, {%1, %2};" : "=l"(r) : "f"(lo), "f"(hi));
    return r;
}
__device__ __forceinline__ ull splat2(float v) { return pack2(v, v); }
__device__ __forceinline__ void unpack2(ull v, float& lo, float& hi) {
    asm("mov.b64 {%0, %1}, %2;" : "=f"(lo), "=f"(hi) : "l"(v));
}
__device__ __forceinline__ ull fma2(ull a, ull b, ull c) {
    ull d;
    asm("fma.rn.f32x2 %0, %1, %2, %3;" : "=l"(d) : "l"(a), "l"(b), "l"(c));
    return d;
}

// ---------- shared memory layout for the edge kernel ----------
struct SMem {
    float h[TILE_E * H_STR];        // silu(radial@W1/sqrt8), padded rows
    float s0[TILE_E * S_STR];       // sh0 * x0[u]
    float s1[TILE_E * S_STR];       // inv_sqrt3 * dot(x1[u,:], sh1)
    float s2[TILE_E * S_STR];       // x0[u]
    float s3[3][TILE_E * S_STR];    // sh0 * x1[u,k]
    float w2b[64 * 256];            // staged W2 block (64 x 256); also reused for radial
    float w1[8 * 64];
    float attr[TILE_E][4];
    int   dste[TILE_E];
    int   srce[TILE_E];
    float lene[TILE_E];
};

__global__ void __launch_bounds__(THREADS, 1)
edge_kernel(const float* __restrict__ x,
            const float* __restrict__ edge_attr,
            const float* __restrict__ edge_len,
            const int*   __restrict__ src,
            const int*   __restrict__ dst,
            const float* __restrict__ W1,
            const float* __restrict__ W2,
            float* __restrict__ out,
            int E)
{
    extern __shared__ float smem_raw[];
    SMem* sm = reinterpret_cast<SMem*>(smem_raw);
    const int tid = threadIdx.x;
    const int e_base = blockIdx.x * TILE_E;

    // ---- load W1 + edge metadata ----
    for (int i = tid; i < 8 * 64; i += THREADS) sm->w1[i] = W1[i];
    if (tid < TILE_E) {
        int e = e_base + tid;
        int ec = e < E ? e : (E - 1);   // clamp: deterministic, epilogue skips invalid
        sm->srce[tid] = src[ec];
        sm->dste[tid] = dst[ec];
        sm->lene[tid] = edge_len[ec];
        float4 a = reinterpret_cast<const float4*>(edge_attr)[ec];
        sm->attr[tid][0] = a.x; sm->attr[tid][1] = a.y;
        sm->attr[tid][2] = a.z; sm->attr[tid][3] = a.w;
    }
    __syncthreads();

    // ---- radial basis (stored temporarily in w2b area) ----
    float* rad = sm->w2b;
    if (tid < TILE_E) {
        float len = sm->lene[tid];
        #pragma unroll
        for (int r = 0; r < 8; r++) {
            float d = len - (5.0f / 7.0f) * (float)r;
            rad[tid * 8 + r] = __expf(-0.5f * d * d);
        }
    }
    __syncthreads();

    // ---- h = silu(radial @ W1 / sqrt(8)) ----
    for (int i = tid; i < TILE_E * 64; i += THREADS) {
        int e = i >> 6, j = i & 63;
        float s = 0.f;
        #pragma unroll
        for (int r = 0; r < 8; r++) s += rad[e * 8 + r] * sm->w1[r * 64 + j];
        s *= INV_SQRT8;
        float hv = s / (1.0f + __expf(-s));
        sm->h[e * H_STR + j] = hv;
    }

    // ---- per-edge s vectors (gather x[src]) ----
    for (int i = tid; i < TILE_E * MUL; i += THREADS) {
        int e = i >> 4, u = i & 15;
        int row = sm->srce[e] * 64;
        float x0  = x[row + u];
        float x10 = x[row + 16 + 3 * u + 0];
        float x11 = x[row + 16 + 3 * u + 1];
        float x12 = x[row + 16 + 3 * u + 2];
        float sh0 = sm->attr[e][0];
        float a1  = sm->attr[e][1], a2 = sm->attr[e][2], a3 = sm->attr[e][3];
        sm->s0[e * S_STR + u] = sh0 * x0;
        sm->s1[e * S_STR + u] = INV_SQRT3 * (x10 * a1 + x11 * a2 + x12 * a3);
        sm->s2[e * S_STR + u] = x0;
        sm->s3[0][e * S_STR + u] = sh0 * x10;
        sm->s3[1][e * S_STR + u] = sh0 * x11;
        sm->s3[2][e * S_STR + u] = sh0 * x12;
    }

    // ---- per-thread mapping: 2 edges x 4 v-columns, all 4 blocks ----
    const int vq = tid & 3;
    const int ep = tid >> 2;          // 0..63
    const int le0 = ep * 2;
    const int v0 = vq * 4;

    ull acc0[2][2], acc2[2][2], acc3[2][3][2];
    #pragma unroll
    for (int i = 0; i < 2; i++) {
        acc0[i][0] = acc0[i][1] = 0ull;
        acc2[i][0] = acc2[i][1] = 0ull;
        #pragma unroll
        for (int k = 0; k < 3; k++) acc3[i][k][0] = acc3[i][k][1] = 0ull;
    }

    const float* hp0 = &sm->h[le0 * H_STR];
    const float* hp1 = &sm->h[(le0 + 1) * H_STR];

    #pragma unroll
    for (int b = 0; b < 4; b++) {
        __syncthreads();   // protect previous block's reads (and phase-A writes for b=0)
        // stage W2 block b: 64 rows x 256 cols
        {
            const float4* W2f4 = reinterpret_cast<const float4*>(W2);
            float4* dstf4 = reinterpret_cast<float4*>(sm->w2b);
            #pragma unroll
            for (int k = 0; k < 16; k++) {
                int i = tid + k * THREADS;        // 0..4095
                int row = i >> 6, c4 = i & 63;
                dstf4[row * 64 + c4] = W2f4[row * 256 + b * 64 + c4];
            }
        }
        __syncthreads();

        #pragma unroll 1
        for (int uc = 0; uc < 4; uc++) {
            ull w[2][4][2];
            #pragma unroll
            for (int i = 0; i < 2; i++)
                #pragma unroll
                for (int j = 0; j < 4; j++) { w[i][j][0] = 0ull; w[i][j][1] = 0ull; }

            const float* wb = &sm->w2b[uc * 64 + v0];
            #pragma unroll 4
            for (int hh = 0; hh < 64; hh++) {
                ull h0 = splat2(hp0[hh]);
                ull h1 = splat2(hp1[hh]);
                const float* wr = wb + hh * 256;
                #pragma unroll
                for (int j = 0; j < 4; j++) {
                    ull wA = *reinterpret_cast<const ull*>(wr + j * 16);
                    ull wB = *reinterpret_cast<const ull*>(wr + j * 16 + 2);
                    w[0][j][0] = fma2(h0, wA, w[0][j][0]);
                    w[0][j][1] = fma2(h0, wB, w[0][j][1]);
                    w[1][j][0] = fma2(h1, wA, w[1][j][0]);
                    w[1][j][1] = fma2(h1, wB, w[1][j][1]);
                }
            }

            // fold this u-chunk into final accumulators via s-vectors
            #pragma unroll
            for (int j = 0; j < 4; j++) {
                const int u = uc * 4 + j;
                #pragma unroll
                for (int i = 0; i < 2; i++) {
                    const int le = le0 + i;
                    if (b == 0) {
                        ull s = splat2(sm->s0[le * S_STR + u]);
                        acc0[i][0] = fma2(s, w[i][j][0], acc0[i][0]);
                        acc0[i][1] = fma2(s, w[i][j][1], acc0[i][1]);
                    } else if (b == 1) {
                        ull s = splat2(sm->s1[le * S_STR + u]);
                        acc0[i][0] = fma2(s, w[i][j][0], acc0[i][0]);
                        acc0[i][1] = fma2(s, w[i][j][1], acc0[i][1]);
                    } else if (b == 2) {
                        ull s = splat2(sm->s2[le * S_STR + u]);
                        acc2[i][0] = fma2(s, w[i][j][0], acc2[i][0]);
                        acc2[i][1] = fma2(s, w[i][j][1], acc2[i][1]);
                    } else {
                        #pragma unroll
                        for (int k = 0; k < 3; k++) {
                            ull s = splat2(sm->s3[k][le * S_STR + u]);
                            acc3[i][k][0] = fma2(s, w[i][j][0], acc3[i][k][0]);
                            acc3[i][k][1] = fma2(s, w[i][j][1], acc3[i][k][1]);
                        }
                    }
                }
            }
        }
    }

    // ---- epilogue: scatter-add into out[dst] ----
    #pragma unroll
    for (int i = 0; i < 2; i++) {
        const int le = le0 + i;
        const int eg = e_base + le;
        if (eg >= E) continue;
        const int drow = sm->dste[le] * 64;
        const float k0 = sm->attr[le][1];
        const float k1 = sm->attr[le][2];
        const float k2 = sm->attr[le][3];
        #pragma unroll
        for (int q = 0; q < 2; q++) {
            float m0a, m0b, t2a, t2b;
            float a30a, a30b, a31a, a31b, a32a, a32b;
            unpack2(acc0[i][q], m0a, m0b);
            unpack2(acc2[i][q], t2a, t2b);
            unpack2(acc3[i][0][q], a30a, a30b);
            unpack2(acc3[i][1][q], a31a, a31b);
            unpack2(acc3[i][2][q], a32a, a32b);
            const int v = v0 + 2 * q;
            atomicAdd(out + drow + v,     SCALE_OUT * m0a);
            atomicAdd(out + drow + v + 1, SCALE_OUT * m0b);
            atomicAdd(out + drow + 16 + 3 * v + 0, SCALE_OUT * (k0 * t2a + a30a));
            atomicAdd(out + drow + 16 + 3 * v + 1, SCALE_OUT * (k1 * t2a + a31a));
            atomicAdd(out + drow + 16 + 3 * v + 2, SCALE_OUT * (k2 * t2a + a32a));
            atomicAdd(out + drow + 16 + 3 * (v + 1) + 0, SCALE_OUT * (k0 * t2b + a30b));
            atomicAdd(out + drow + 16 + 3 * (v + 1) + 1, SCALE_OUT * (k1 * t2b + a31b));
            atomicAdd(out + drow + 16 + 3 * (v + 1) + 2, SCALE_OUT * (k2 * t2b + a32b));
        }
    }
}

// ---------- self-connection: out[n] = concat(x0@L0, einsum(x1,L1)) / sqrt(MUL) ----------
__global__ void sc_kernel(const float* __restrict__ x,
                          const float* __restrict__ L0,
                          const float* __restrict__ L1,
                          float* __restrict__ out,
                          int Nnodes)
{
    __shared__ float l0[256], l1[256];
    int t = threadIdx.x;
    l0[t] = L0[t];
    l1[t] = L1[t];
    __syncthreads();

    int n = blockIdx.x * blockDim.x + t;
    if (n >= Nnodes) return;

    float xv[64];
    const float4* xr = reinterpret_cast<const float4*>(x + (size_t)n * 64);
    #pragma unroll
    for (int i = 0; i < 16; i++) {
        float4 v = xr[i];
        xv[4 * i + 0] = v.x; xv[4 * i + 1] = v.y;
        xv[4 * i + 2] = v.z; xv[4 * i + 3] = v.w;
    }

    float* orow = out + (size_t)n * 64;
    #pragma unroll
    for (int v = 0; v < 16; v++) {
        float s = 0.f;
        #pragma unroll
        for (int u = 0; u < 16; u++) s += xv[u] * l0[u * 16 + v];
        orow[v] = INV_SQRT_MUL * s;
    }
    #pragma unroll
    for (int v = 0; v < 16; v++) {
        float sk0 = 0.f, sk1 = 0.f, sk2 = 0.f;
        #pragma unroll
        for (int u = 0; u < 16; u++) {
            float L = l1[u * 16 + v];
            sk0 += xv[16 + 3 * u + 0] * L;
            sk1 += xv[16 + 3 * u + 1] * L;
            sk2 += xv[16 + 3 * u + 2] * L;
        }
        orow[16 + 3 * v + 0] = INV_SQRT_MUL * sk0;
        orow[16 + 3 * v + 1] = INV_SQRT_MUL * sk1;
        orow[16 + 3 * v + 2] = INV_SQRT_MUL * sk2;
    }
}

extern "C" void kernel_launch(void* const* d_in, const int* in_sizes, int n_in,
                              void* d_out, int out_size)
{
    const float* x         = (const float*)d_in[0];
    const float* edge_attr = (const float*)d_in[1];
    const float* edge_len  = (const float*)d_in[2];
    const int*   src       = (const int*)d_in[3];
    const int*   dst       = (const int*)d_in[4];
    const float* W1        = (const float*)d_in[5];
    const float* W2        = (const float*)d_in[6];
    const float* L0        = (const float*)d_in[7];
    const float* L1        = (const float*)d_in[8];
    float* out = (float*)d_out;

    const int E = in_sizes[2];              // edge_length element count
    const int Nnodes = in_sizes[0] / 64;    // x is (N, 64)

    const int smem_bytes = (int)sizeof(SMem);
    cudaFuncSetAttribute(edge_kernel, cudaFuncAttributeMaxDynamicSharedMemorySize, smem_bytes);

    // self-connection initializes ALL of out, then edge kernel atomically accumulates
    sc_kernel<<<(Nnodes + 255) / 256, 256>>>(x, L0, L1, out, Nnodes);
    edge_kernel<<<(E + TILE_E - 1) / TILE_E, THREADS, smem_bytes>>>(
        x, edge_attr, edge_len, src, dst, W1, W2, out, E);
}

// round 5
// speedup vs baseline: 1.7216x; 1.7216x over previous
#include <cuda_runtime.h>
#include <cuda_bf16.h>
#include <cstdint>

typedef unsigned int u32;
typedef unsigned long long u64;

#define THREADS 256
#define TILE_E 128

#define INV_SQRT3 0.5773502691896258f
#define INV_SQRT8 0.35355339059327373f
#define SCALE_OUT 0.022097086912079608f   // PATH_ALPHA / sqrt(HIDDEN)
#define INV_SQRT_MUL 0.25f

// ---- shared memory byte offsets (from 1024-aligned base) ----
#define OFF_A_HI 0          // 128 rows x 128B (64 bf16), swizzled
#define OFF_A_LO 16384
#define OFF_B    32768      // 2 buffers x 65536 (hi 32768 | lo 32768)
#define OFF_S    163840     // float[6][16][128] = 49152
#define OFF_RAD  212992     // float[128][8]
#define OFF_W1   217088     // float[512]
#define OFF_ATTR 219136     // float[128][4]
#define OFF_DST  221184     // int[128]
#define OFF_SRC  221696     // int[128]
#define SMEM_BYTES (222208 + 1024)

// W2 pre-transposed + hi/lo split: [m(1024)][k(64)] bf16 (B^T row-major)
__device__ __align__(16) __nv_bfloat16 g_w2t_hi[1024 * 64];
__device__ __align__(16) __nv_bfloat16 g_w2t_lo[1024 * 64];

// ---------------- PTX helpers ----------------
__device__ __forceinline__ u32 smem_u32(const void* p) {
    u32 a;
    asm("{ .reg .u64 t; cvta.to.shared.u64 t, %1; cvt.u32.u64 %0, t; }"
        : "=r"(a) : "l"(p));
    return a;
}
__device__ __forceinline__ u32 swz(u32 row, u32 kb) {
    return row * 128 + (kb ^ ((row & 7) << 4));
}
__device__ __forceinline__ void ldsm4(u32* r, u32 addr) {
    asm volatile("ldmatrix.sync.aligned.m8n8.x4.shared.b16 {%0,%1,%2,%3}, [%4];"
                 : "=r"(r[0]), "=r"(r[1]), "=r"(r[2]), "=r"(r[3]) : "r"(addr));
}
__device__ __forceinline__ void mma16816(float* d, const u32* a, const u32* b) {
    asm volatile("mma.sync.aligned.m16n8k16.row.col.f32.bf16.bf16.f32 "
                 "{%0,%1,%2,%3}, {%4,%5,%6,%7}, {%8,%9}, {%0,%1,%2,%3};"
                 : "+f"(d[0]), "+f"(d[1]), "+f"(d[2]), "+f"(d[3])
                 : "r"(a[0]), "r"(a[1]), "r"(a[2]), "r"(a[3]),
                   "r"(b[0]), "r"(b[1]));
}
__device__ __forceinline__ void cp16(u32 dst, const void* src) {
    asm volatile("cp.async.cg.shared.global [%0], [%1], 16;" :: "r"(dst), "l"(src));
}
#define CP_COMMIT() asm volatile("cp.async.commit_group;" ::: "memory")
#define CP_WAIT(n)  asm volatile("cp.async.wait_group %0;" :: "n"(n) : "memory")

typedef unsigned long long ull;
__device__ __forceinline__ ull pack2(float lo, float hi) {
    ull r; asm("mov.b64 %0, {%1, %2};" : "=l"(r) : "f"(lo), "f"(hi)); return r;
}
__device__ __forceinline__ ull splat2(float v) { return pack2(v, v); }
__device__ __forceinline__ void unpack2(ull v, float& lo, float& hi) {
    asm("mov.b64 {%0, %1}, %2;" : "=f"(lo), "=f"(hi) : "l"(v));
}
__device__ __forceinline__ ull fma2(ull a, ull b, ull c) {
    ull d; asm("fma.rn.f32x2 %0, %1, %2, %3;" : "=l"(d) : "l"(a), "l"(b), "l"(c)); return d;
}
__device__ __forceinline__ void red2(float* p, float a, float b) {
    asm volatile("red.global.add.v2.f32 [%0], {%1,%2};" :: "l"(p), "f"(a), "f"(b) : "memory");
}

// ---------------- prep: transpose + hi/lo split W2 ----------------
__global__ void prep_w2(const float* __restrict__ W2) {
    int i = blockIdx.x * 256 + threadIdx.x;   // over 64*1024
    float v = W2[i];
    int k = i >> 10, m = i & 1023;
    __nv_bfloat16 hi = __float2bfloat16(v);
    __nv_bfloat16 lo = __float2bfloat16(v - __bfloat162float(hi));
    g_w2t_hi[m * 64 + k] = hi;
    g_w2t_lo[m * 64 + k] = lo;
}

// ---------------- B staging: block b -> buffer buf (swizzled) ----------------
__device__ __forceinline__ void prefetchB(u32 sbase, int b, int buf, int tid) {
    const char* gh = (const char*)g_w2t_hi + b * 32768;
    const char* gl = (const char*)g_w2t_lo + b * 32768;
    u32 dhi = sbase + OFF_B + buf * 65536;
    u32 dlo = dhi + 32768;
    #pragma unroll
    for (int it = 0; it < 8; it++) {
        int i = tid + it * THREADS;           // 0..2047 16B chunks
        u32 row = (u32)(i >> 3), c16 = (u32)((i & 7) * 16);
        u32 off = swz(row, c16);
        cp16(dhi + off, gh + (size_t)i * 16);
        cp16(dlo + off, gl + (size_t)i * 16);
    }
    CP_COMMIT();
}

// ---------------- main edge kernel ----------------
__global__ void __launch_bounds__(THREADS, 1)
edge_mma_kernel(const float* __restrict__ x,
                const float* __restrict__ edge_attr,
                const float* __restrict__ edge_len,
                const int* __restrict__ src,
                const int* __restrict__ dst,
                const float* __restrict__ W1,
                float* __restrict__ out,
                int E)
{
    extern __shared__ char smem_raw[];
    char* smem = (char*)((((size_t)smem_raw) + 1023) & ~(size_t)1023);
    const u32 sbase = smem_u32(smem);
    const int tid = threadIdx.x;
    const int wid = tid >> 5;
    const int lane = tid & 31;
    const int e_base = blockIdx.x * TILE_E;

    // start streaming B block 0 immediately
    prefetchB(sbase, 0, 0, tid);

    float* w1s  = (float*)(smem + OFF_W1);
    float* attr = (float*)(smem + OFF_ATTR);
    int*   dsts = (int*)(smem + OFF_DST);
    int*   srcs = (int*)(smem + OFF_SRC);
    float* rad  = (float*)(smem + OFF_RAD);
    float* Sf   = (float*)(smem + OFF_S);

    for (int i = tid; i < 512; i += THREADS) w1s[i] = W1[i];

    if (tid < TILE_E) {
        int e = e_base + tid;
        int ec = e < E ? e : E - 1;      // clamp; epilogue predicates
        srcs[tid] = src[ec];
        dsts[tid] = dst[ec];
        float len = edge_len[ec];
        float4 a = reinterpret_cast<const float4*>(edge_attr)[ec];
        attr[tid * 4 + 0] = a.x; attr[tid * 4 + 1] = a.y;
        attr[tid * 4 + 2] = a.z; attr[tid * 4 + 3] = a.w;
        #pragma unroll
        for (int r = 0; r < 8; r++) {
            float d = len - (5.0f / 7.0f) * (float)r;
            rad[tid * 8 + r] = __expf(-0.5f * d * d);
        }
    }
    __syncthreads();

    // h = silu(radial @ W1 / sqrt(8)) -> split bf16 A tiles (swizzled rows of 128B)
    for (int i = tid; i < TILE_E * 64; i += THREADS) {
        int e = i >> 6, j = i & 63;
        float s = 0.f;
        #pragma unroll
        for (int r = 0; r < 8; r++) s += rad[e * 8 + r] * w1s[r * 64 + j];
        s *= INV_SQRT8;
        float hv = s / (1.0f + __expf(-s));
        __nv_bfloat16 hi = __float2bfloat16(hv);
        __nv_bfloat16 lo = __float2bfloat16(hv - __bfloat162float(hi));
        u32 off = swz((u32)e, (u32)(j * 2));
        *reinterpret_cast<__nv_bfloat16*>(smem + OFF_A_HI + off) = hi;
        *reinterpret_cast<__nv_bfloat16*>(smem + OFF_A_LO + off) = lo;
    }

    // per-edge s vectors: S[fam][u][e]
    for (int i = tid; i < TILE_E * 16; i += THREADS) {
        int e = i & 127, u = i >> 7;
        int row = srcs[e] * 64;
        float x0  = x[row + u];
        float x10 = x[row + 16 + 3 * u + 0];
        float x11 = x[row + 16 + 3 * u + 1];
        float x12 = x[row + 16 + 3 * u + 2];
        float sh0 = attr[e * 4 + 0];
        float a1 = attr[e * 4 + 1], a2 = attr[e * 4 + 2], a3 = attr[e * 4 + 3];
        Sf[(0 * 16 + u) * 128 + e] = sh0 * x0;
        Sf[(1 * 16 + u) * 128 + e] = INV_SQRT3 * (x10 * a1 + x11 * a2 + x12 * a3);
        Sf[(2 * 16 + u) * 128 + e] = x0;
        Sf[(3 * 16 + u) * 128 + e] = sh0 * x10;
        Sf[(4 * 16 + u) * 128 + e] = sh0 * x11;
        Sf[(5 * 16 + u) * 128 + e] = sh0 * x12;
    }
    __syncthreads();   // A tiles + S ready

    // ---- preload A fragments (hi/lo, 4 k-tiles each) ----
    u32 Ahi[4][4], Alo[4][4];
    {
        u32 grp = (u32)(lane >> 3), r = (u32)(lane & 7);
        u32 arow = (u32)(wid * 16) + r + (grp & 1) * 8;
        u32 akb  = (grp >> 1) * 16;
        #pragma unroll
        for (int kt = 0; kt < 4; kt++) {
            u32 off = swz(arow, akb + (u32)kt * 32);
            ldsm4(Ahi[kt], sbase + OFF_A_HI + off);
            ldsm4(Alo[kt], sbase + OFF_A_LO + off);
        }
    }

    // accumulators: [fam 0..4][edge 0..1][vpair 0..1] as f32x2
    ull acc[5][2][2];
    #pragma unroll
    for (int f = 0; f < 5; f++)
        #pragma unroll
        for (int e = 0; e < 2; e++) { acc[f][e][0] = 0ull; acc[f][e][1] = 0ull; }

    const int eoff = wid * 16 + (lane >> 2);   // e0 local index

    #pragma unroll
    for (int b = 0; b < 4; b++) {
        if (b < 3) prefetchB(sbase, b + 1, (b + 1) & 1, tid);
        if (b < 3) { CP_WAIT(1); } else { CP_WAIT(0); }
        __syncthreads();   // buffer b visible to all; prev buffer released

        const u32 bbase_hi = sbase + OFF_B + (u32)((b & 1) * 65536);
        const u32 bbase_lo = bbase_hi + 32768;
        const u32 brow_r = (u32)(lane & 7);
        const u32 bkb_g  = (u32)((lane >> 3) * 16);

        #pragma unroll 2
        for (int ntp = 0; ntp < 16; ntp++) {
            const u32 n0 = (u32)(2 * ntp * 8);
            const u32 n1 = n0 + 8;
            u32 bh0[4][2], bh1[4][2], bl0[4][2], bl1[4][2];
            #pragma unroll
            for (int h = 0; h < 2; h++) {
                u32 kb = (u32)h * 64 + bkb_g;
                u32 t[4];
                ldsm4(t, bbase_hi + swz(n0 + brow_r, kb));
                bh0[2*h][0]=t[0]; bh0[2*h][1]=t[1]; bh0[2*h+1][0]=t[2]; bh0[2*h+1][1]=t[3];
                ldsm4(t, bbase_hi + swz(n1 + brow_r, kb));
                bh1[2*h][0]=t[0]; bh1[2*h][1]=t[1]; bh1[2*h+1][0]=t[2]; bh1[2*h+1][1]=t[3];
                ldsm4(t, bbase_lo + swz(n0 + brow_r, kb));
                bl0[2*h][0]=t[0]; bl0[2*h][1]=t[1]; bl0[2*h+1][0]=t[2]; bl0[2*h+1][1]=t[3];
                ldsm4(t, bbase_lo + swz(n1 + brow_r, kb));
                bl1[2*h][0]=t[0]; bl1[2*h][1]=t[1]; bl1[2*h+1][0]=t[2]; bl1[2*h+1][1]=t[3];
            }

            float d0[4] = {0.f, 0.f, 0.f, 0.f};
            float d1[4] = {0.f, 0.f, 0.f, 0.f};
            #pragma unroll
            for (int kt = 0; kt < 4; kt++) { mma16816(d0, Ahi[kt], bh0[kt]); mma16816(d1, Ahi[kt], bh1[kt]); }
            #pragma unroll
            for (int kt = 0; kt < 4; kt++) { mma16816(d0, Alo[kt], bh0[kt]); mma16816(d1, Alo[kt], bh1[kt]); }
            #pragma unroll
            for (int kt = 0; kt < 4; kt++) { mma16816(d0, Ahi[kt], bl0[kt]); mma16816(d1, Ahi[kt], bl1[kt]); }

            // fold: u = ntp; nt0 -> v pair 0 (v=2q), nt1 -> pair 1 (v=8+2q)
            if (b == 0 || b == 1) {
                const float* sp = &Sf[(b * 16 + ntp) * 128 + eoff];
                #pragma unroll
                for (int e = 0; e < 2; e++) {
                    ull s = splat2(sp[8 * e]);
                    acc[0][e][0] = fma2(s, pack2(d0[2*e], d0[2*e+1]), acc[0][e][0]);
                    acc[0][e][1] = fma2(s, pack2(d1[2*e], d1[2*e+1]), acc[0][e][1]);
                }
            } else if (b == 2) {
                const float* sp = &Sf[(2 * 16 + ntp) * 128 + eoff];
                #pragma unroll
                for (int e = 0; e < 2; e++) {
                    ull s = splat2(sp[8 * e]);
                    acc[1][e][0] = fma2(s, pack2(d0[2*e], d0[2*e+1]), acc[1][e][0]);
                    acc[1][e][1] = fma2(s, pack2(d1[2*e], d1[2*e+1]), acc[1][e][1]);
                }
            } else {
                #pragma unroll
                for (int k = 0; k < 3; k++) {
                    const float* sp = &Sf[((3 + k) * 16 + ntp) * 128 + eoff];
                    #pragma unroll
                    for (int e = 0; e < 2; e++) {
                        ull s = splat2(sp[8 * e]);
                        acc[2+k][e][0] = fma2(s, pack2(d0[2*e], d0[2*e+1]), acc[2+k][e][0]);
                        acc[2+k][e][1] = fma2(s, pack2(d1[2*e], d1[2*e+1]), acc[2+k][e][1]);
                    }
                }
            }
        }
        __syncthreads();   // release buffer b
    }

    // ---- epilogue: scatter-add via vector reds ----
    const int q = lane & 3;
    #pragma unroll
    for (int e = 0; e < 2; e++) {
        const int el = eoff + 8 * e;
        const int eg = e_base + el;
        if (eg >= E) continue;
        float* op = out + (size_t)dsts[el] * 64;
        const float k0 = attr[el * 4 + 1];
        const float k1 = attr[el * 4 + 2];
        const float k2 = attr[el * 4 + 3];

        #pragma unroll
        for (int p = 0; p < 2; p++) {
            float m0a, m0b, ta, tb;
            float a0a, a0b, a1a, a1b, a2a, a2b;
            unpack2(acc[0][e][p], m0a, m0b);
            unpack2(acc[1][e][p], ta, tb);
            unpack2(acc[2][e][p], a0a, a0b);
            unpack2(acc[3][e][p], a1a, a1b);
            unpack2(acc[4][e][p], a2a, a2b);
            const int v = 8 * p + 2 * q;
            red2(op + v, SCALE_OUT * m0a, SCALE_OUT * m0b);
            const int base = 16 + 3 * v;
            red2(op + base,     SCALE_OUT * fmaf(k0, ta, a0a), SCALE_OUT * fmaf(k1, ta, a1a));
            red2(op + base + 2, SCALE_OUT * fmaf(k2, ta, a2a), SCALE_OUT * fmaf(k0, tb, a0b));
            red2(op + base + 4, SCALE_OUT * fmaf(k1, tb, a1b), SCALE_OUT * fmaf(k2, tb, a2b));
        }
    }
}

// ---------- self-connection (initializes all of out) ----------
__global__ void sc_kernel(const float* __restrict__ x,
                          const float* __restrict__ L0,
                          const float* __restrict__ L1,
                          float* __restrict__ out,
                          int Nnodes)
{
    __shared__ float l0[256], l1[256];
    int t = threadIdx.x;
    l0[t] = L0[t];
    l1[t] = L1[t];
    __syncthreads();

    int n = blockIdx.x * blockDim.x + t;
    if (n >= Nnodes) return;

    float xv[64];
    const float4* xr = reinterpret_cast<const float4*>(x + (size_t)n * 64);
    #pragma unroll
    for (int i = 0; i < 16; i++) {
        float4 v = xr[i];
        xv[4 * i + 0] = v.x; xv[4 * i + 1] = v.y;
        xv[4 * i + 2] = v.z; xv[4 * i + 3] = v.w;
    }

    float* orow = out + (size_t)n * 64;
    #pragma unroll
    for (int v = 0; v < 16; v++) {
        float s = 0.f;
        #pragma unroll
        for (int u = 0; u < 16; u++) s += xv[u] * l0[u * 16 + v];
        orow[v] = INV_SQRT_MUL * s;
    }
    #pragma unroll
    for (int v = 0; v < 16; v++) {
        float sk0 = 0.f, sk1 = 0.f, sk2 = 0.f;
        #pragma unroll
        for (int u = 0; u < 16; u++) {
            float L = l1[u * 16 + v];
            sk0 += xv[16 + 3 * u + 0] * L;
            sk1 += xv[16 + 3 * u + 1] * L;
            sk2 += xv[16 + 3 * u + 2] * L;
        }
        orow[16 + 3 * v + 0] = INV_SQRT_MUL * sk0;
        orow[16 + 3 * v + 1] = INV_SQRT_MUL * sk1;
        orow[16 + 3 * v + 2] = INV_SQRT_MUL * sk2;
    }
}

extern "C" void kernel_launch(void* const* d_in, const int* in_sizes, int n_in,
                              void* d_out, int out_size)
{
    const float* x         = (const float*)d_in[0];
    const float* edge_attr = (const float*)d_in[1];
    const float* edge_len  = (const float*)d_in[2];
    const int*   src       = (const int*)d_in[3];
    const int*   dst       = (const int*)d_in[4];
    const float* W1        = (const float*)d_in[5];
    const float* W2        = (const float*)d_in[6];
    const float* L0        = (const float*)d_in[7];
    const float* L1        = (const float*)d_in[8];
    float* out = (float*)d_out;

    const int E = in_sizes[2];
    const int Nnodes = in_sizes[0] / 64;

    cudaFuncSetAttribute(edge_mma_kernel, cudaFuncAttributeMaxDynamicSharedMemorySize, SMEM_BYTES);

    prep_w2<<<256, 256>>>(W2);
    sc_kernel<<<(Nnodes + 255) / 256, 256>>>(x, L0, L1, out, Nnodes);
    edge_mma_kernel<<<(E + TILE_E - 1) / TILE_E, THREADS, SMEM_BYTES>>>(
        x, edge_attr, edge_len, src, dst, W1, out, E);
}

// round 7
// speedup vs baseline: 2.6675x; 1.5494x over previous
#include <cuda_runtime.h>
#include <cuda_bf16.h>
#include <cstdint>

typedef unsigned int u32;
typedef unsigned long long u64;

#define THREADS 256
#define TILE_E 128

#define INV_SQRT3 0.5773502691896258f
#define INV_SQRT8 0.35355339059327373f
#define SCALE_OUT 0.022097086912079608f   // PATH_ALPHA / sqrt(HIDDEN)
#define INV_SQRT_MUL 0.25f

// ---- shared memory byte offsets (from 1024-aligned base) ----
#define OFF_A_HI 0          // 128 rows x 128B (64 bf16), swizzled
#define OFF_A_LO 16384
#define OFF_B    32768      // 2 buffers x 65536 (hi 32768 | lo 32768)
#define OFF_S    163840     // float[6][16][128] = 49152
#define OFF_RAD  212992     // float[128][8]
#define OFF_W1   217088     // float[512]
#define OFF_ATTR 219136     // float[128][4]
#define OFF_DST  221184     // int[128]
#define OFF_SRC  221696     // int[128]
#define SMEM_BYTES (222208 + 1024)

// W2 pre-transposed + hi/lo split: [m(1024)][k(64)] bf16 (B^T row-major)
__device__ __align__(16) __nv_bfloat16 g_w2t_hi[1024 * 64];
__device__ __align__(16) __nv_bfloat16 g_w2t_lo[1024 * 64];

// ---------------- PTX helpers ----------------
__device__ __forceinline__ u32 smem_u32(const void* p) {
    u32 a;
    asm("{ .reg .u64 t; cvta.to.shared.u64 t, %1; cvt.u32.u64 %0, t; }"
        : "=r"(a) : "l"(p));
    return a;
}
__device__ __forceinline__ u32 swz(u32 row, u32 kb) {
    return row * 128 + (kb ^ ((row & 7) << 4));
}
__device__ __forceinline__ void ldsm4(u32* r, u32 addr) {
    asm volatile("ldmatrix.sync.aligned.m8n8.x4.shared.b16 {%0,%1,%2,%3}, [%4];"
                 : "=r"(r[0]), "=r"(r[1]), "=r"(r[2]), "=r"(r[3]) : "r"(addr));
}
__device__ __forceinline__ void mma16816(float* d, const u32* a, const u32* b) {
    asm volatile("mma.sync.aligned.m16n8k16.row.col.f32.bf16.bf16.f32 "
                 "{%0,%1,%2,%3}, {%4,%5,%6,%7}, {%8,%9}, {%0,%1,%2,%3};"
                 : "+f"(d[0]), "+f"(d[1]), "+f"(d[2]), "+f"(d[3])
                 : "r"(a[0]), "r"(a[1]), "r"(a[2]), "r"(a[3]),
                   "r"(b[0]), "r"(b[1]));
}
__device__ __forceinline__ void cp16(u32 dst, const void* src) {
    asm volatile("cp.async.cg.shared.global [%0], [%1], 16;" :: "r"(dst), "l"(src));
}
#define CP_COMMIT() asm volatile("cp.async.commit_group;" ::: "memory")
#define CP_WAIT(n)  asm volatile("cp.async.wait_group %0;" :: "n"(n) : "memory")

typedef unsigned long long ull;
__device__ __forceinline__ ull pack2(float lo, float hi) {
    ull r; asm("mov.b64 %0, {%1, %2};" : "=l"(r) : "f"(lo), "f"(hi)); return r;
}
__device__ __forceinline__ ull splat2(float v) { return pack2(v, v); }
__device__ __forceinline__ void unpack2(ull v, float& lo, float& hi) {
    asm("mov.b64 {%0, %1}, %2;" : "=f"(lo), "=f"(hi) : "l"(v));
}
__device__ __forceinline__ ull fma2(ull a, ull b, ull c) {
    ull d; asm("fma.rn.f32x2 %0, %1, %2, %3;" : "=l"(d) : "l"(a), "l"(b), "l"(c)); return d;
}
__device__ __forceinline__ void red2(float* p, float a, float b) {
    asm volatile("red.global.add.v2.f32 [%0], {%1,%2};" :: "l"(p), "f"(a), "f"(b) : "memory");
}

// ---------------- prep: transpose + hi/lo split W2 ----------------
__global__ void prep_w2(const float* __restrict__ W2) {
    int i = blockIdx.x * 256 + threadIdx.x;   // over 64*1024
    float v = W2[i];
    int k = i >> 10, m = i & 1023;
    __nv_bfloat16 hi = __float2bfloat16(v);
    __nv_bfloat16 lo = __float2bfloat16(v - __bfloat162float(hi));
    g_w2t_hi[m * 64 + k] = hi;
    g_w2t_lo[m * 64 + k] = lo;
}

// ---------------- B staging: block b -> buffer buf (swizzled) ----------------
__device__ __forceinline__ void prefetchB(u32 sbase, int b, int buf, int tid) {
    const char* gh = (const char*)g_w2t_hi + b * 32768;
    const char* gl = (const char*)g_w2t_lo + b * 32768;
    u32 dhi = sbase + OFF_B + buf * 65536;
    u32 dlo = dhi + 32768;
    #pragma unroll
    for (int it = 0; it < 8; it++) {
        int i = tid + it * THREADS;           // 0..2047 16B chunks
        u32 row = (u32)(i >> 3), c16 = (u32)((i & 7) * 16);
        u32 off = swz(row, c16);
        cp16(dhi + off, gh + (size_t)i * 16);
        cp16(dlo + off, gl + (size_t)i * 16);
    }
    CP_COMMIT();
}

// load one 16x16 (n-rows x k) B fragment group: dst[kt 0..3][2]
__device__ __forceinline__ void ldB(u32 dst[4][2], u32 base, u32 nrow,
                                    u32 brow_r, u32 bkb_g) {
    #pragma unroll
    for (int h = 0; h < 2; h++) {
        u32 t[4];
        ldsm4(t, base + swz(nrow + brow_r, (u32)h * 64 + bkb_g));
        dst[2*h][0] = t[0]; dst[2*h][1] = t[1];
        dst[2*h+1][0] = t[2]; dst[2*h+1][1] = t[3];
    }
}

// ---------------- main edge kernel ----------------
__global__ void __launch_bounds__(THREADS, 1)
edge_mma_kernel(const float* __restrict__ x,
                const float* __restrict__ edge_attr,
                const float* __restrict__ edge_len,
                const int* __restrict__ src,
                const int* __restrict__ dst,
                const float* __restrict__ W1,
                float* __restrict__ out,
                int E)
{
    extern __shared__ char smem_raw[];
    char* smem = (char*)((((size_t)smem_raw) + 1023) & ~(size_t)1023);
    const u32 sbase = smem_u32(smem);
    const int tid = threadIdx.x;
    const int wid = tid >> 5;
    const int lane = tid & 31;
    const int e_base = blockIdx.x * TILE_E;

    // start streaming B block 0 immediately
    prefetchB(sbase, 0, 0, tid);

    float* w1s  = (float*)(smem + OFF_W1);
    float* attr = (float*)(smem + OFF_ATTR);
    int*   dsts = (int*)(smem + OFF_DST);
    int*   srcs = (int*)(smem + OFF_SRC);
    float* rad  = (float*)(smem + OFF_RAD);
    float* Sf   = (float*)(smem + OFF_S);

    for (int i = tid; i < 512; i += THREADS) w1s[i] = W1[i];

    if (tid < TILE_E) {
        int e = e_base + tid;
        int ec = e < E ? e : E - 1;      // clamp; epilogue predicates
        srcs[tid] = src[ec];
        dsts[tid] = dst[ec];
        float len = edge_len[ec];
        float4 a = reinterpret_cast<const float4*>(edge_attr)[ec];
        attr[tid * 4 + 0] = a.x; attr[tid * 4 + 1] = a.y;
        attr[tid * 4 + 2] = a.z; attr[tid * 4 + 3] = a.w;
        #pragma unroll
        for (int r = 0; r < 8; r++) {
            float d = len - (5.0f / 7.0f) * (float)r;
            rad[tid * 8 + r] = __expf(-0.5f * d * d);
        }
    }
    __syncthreads();

    // h = silu(radial @ W1 / sqrt(8)) -> split bf16 A tiles (swizzled rows of 128B)
    for (int i = tid; i < TILE_E * 64; i += THREADS) {
        int e = i >> 6, j = i & 63;
        float s = 0.f;
        #pragma unroll
        for (int r = 0; r < 8; r++) s += rad[e * 8 + r] * w1s[r * 64 + j];
        s *= INV_SQRT8;
        float hv = s / (1.0f + __expf(-s));
        __nv_bfloat16 hi = __float2bfloat16(hv);
        __nv_bfloat16 lo = __float2bfloat16(hv - __bfloat162float(hi));
        u32 off = swz((u32)e, (u32)(j * 2));
        *reinterpret_cast<__nv_bfloat16*>(smem + OFF_A_HI + off) = hi;
        *reinterpret_cast<__nv_bfloat16*>(smem + OFF_A_LO + off) = lo;
    }

    // per-edge s vectors: S[fam][u][e]
    for (int i = tid; i < TILE_E * 16; i += THREADS) {
        int e = i & 127, u = i >> 7;
        int row = srcs[e] * 64;
        float x0  = x[row + u];
        float x10 = x[row + 16 + 3 * u + 0];
        float x11 = x[row + 16 + 3 * u + 1];
        float x12 = x[row + 16 + 3 * u + 2];
        float sh0 = attr[e * 4 + 0];
        float a1 = attr[e * 4 + 1], a2 = attr[e * 4 + 2], a3 = attr[e * 4 + 3];
        Sf[(0 * 16 + u) * 128 + e] = sh0 * x0;
        Sf[(1 * 16 + u) * 128 + e] = INV_SQRT3 * (x10 * a1 + x11 * a2 + x12 * a3);
        Sf[(2 * 16 + u) * 128 + e] = x0;
        Sf[(3 * 16 + u) * 128 + e] = sh0 * x10;
        Sf[(4 * 16 + u) * 128 + e] = sh0 * x11;
        Sf[(5 * 16 + u) * 128 + e] = sh0 * x12;
    }
    __syncthreads();   // A tiles + S ready

    // ---- preload A fragments (hi/lo, 4 k-tiles each) ----
    u32 Ahi[4][4], Alo[4][4];
    {
        u32 grp = (u32)(lane >> 3), r = (u32)(lane & 7);
        u32 arow = (u32)(wid * 16) + r + (grp & 1) * 8;
        u32 akb  = (grp >> 1) * 16;
        #pragma unroll
        for (int kt = 0; kt < 4; kt++) {
            u32 off = swz(arow, akb + (u32)kt * 32);
            ldsm4(Ahi[kt], sbase + OFF_A_HI + off);
            ldsm4(Alo[kt], sbase + OFF_A_LO + off);
        }
    }

    // accumulators: [fam 0..4][edge 0..1][vpair 0..1] as f32x2
    ull acc[5][2][2];
    #pragma unroll
    for (int f = 0; f < 5; f++)
        #pragma unroll
        for (int e = 0; e < 2; e++) { acc[f][e][0] = 0ull; acc[f][e][1] = 0ull; }

    const int eoff = wid * 16 + (lane >> 2);   // e0 local index

    #pragma unroll
    for (int b = 0; b < 4; b++) {
        if (b < 3) prefetchB(sbase, b + 1, (b + 1) & 1, tid);
        if (b < 3) { CP_WAIT(1); } else { CP_WAIT(0); }
        __syncthreads();   // buffer b visible to all; prev buffer released

        const u32 bbase_hi = sbase + OFF_B + (u32)((b & 1) * 65536);
        const u32 bbase_lo = bbase_hi + 32768;
        const u32 brow_r = (u32)(lane & 7);
        const u32 bkb_g  = (u32)((lane >> 3) * 16);

        // register double-buffer for hi B fragments (pipelined one ntp ahead)
        u32 BH0[2][4][2], BH1[2][4][2];
        ldB(BH0[0], bbase_hi, 0, brow_r, bkb_g);
        ldB(BH1[0], bbase_hi, 8, brow_r, bkb_g);

        #pragma unroll 2
        for (int ntp = 0; ntp < 16; ntp++) {
            const int cur = ntp & 1, nxt = cur ^ 1;
            const u32 n0 = (u32)(2 * ntp * 8);
            const u32 n1 = n0 + 8;

            // prefetch next ntp's hi fragments (consumed next iteration)
            if (ntp < 15) {
                ldB(BH0[nxt], bbase_hi, n0 + 16, brow_r, bkb_g);
                ldB(BH1[nxt], bbase_hi, n1 + 16, brow_r, bkb_g);
            }
            // lo fragments for this ntp (consumed after 16 hi-MMAs in flight)
            u32 BL0[4][2], BL1[4][2];
            ldB(BL0, bbase_lo, n0, brow_r, bkb_g);
            ldB(BL1, bbase_lo, n1, brow_r, bkb_g);

            // 6 independent MMA chains, depth 4 each
            float c0[4] = {0,0,0,0}, c1[4] = {0,0,0,0}, c2[4] = {0,0,0,0};
            float c3[4] = {0,0,0,0}, c4[4] = {0,0,0,0}, c5[4] = {0,0,0,0};
            #pragma unroll
            for (int kt = 0; kt < 4; kt++) {
                mma16816(c0, Ahi[kt], BH0[cur][kt]);
                mma16816(c3, Ahi[kt], BH1[cur][kt]);
                mma16816(c1, Alo[kt], BH0[cur][kt]);
                mma16816(c4, Alo[kt], BH1[cur][kt]);
            }
            #pragma unroll
            for (int kt = 0; kt < 4; kt++) {
                mma16816(c2, Ahi[kt], BL0[kt]);
                mma16816(c5, Ahi[kt], BL1[kt]);
            }

            float d0[4], d1[4];
            #pragma unroll
            for (int i = 0; i < 4; i++) {
                d0[i] = (c0[i] + c1[i]) + c2[i];
                d1[i] = (c3[i] + c4[i]) + c5[i];
            }

            // fold: u = ntp; nt0 -> v pair 0 (v=2q), nt1 -> pair 1 (v=8+2q)
            if (b == 0 || b == 1) {
                const float* sp = &Sf[(b * 16 + ntp) * 128 + eoff];
                #pragma unroll
                for (int e = 0; e < 2; e++) {
                    ull s = splat2(sp[8 * e]);
                    acc[0][e][0] = fma2(s, pack2(d0[2*e], d0[2*e+1]), acc[0][e][0]);
                    acc[0][e][1] = fma2(s, pack2(d1[2*e], d1[2*e+1]), acc[0][e][1]);
                }
            } else if (b == 2) {
                const float* sp = &Sf[(2 * 16 + ntp) * 128 + eoff];
                #pragma unroll
                for (int e = 0; e < 2; e++) {
                    ull s = splat2(sp[8 * e]);
                    acc[1][e][0] = fma2(s, pack2(d0[2*e], d0[2*e+1]), acc[1][e][0]);
                    acc[1][e][1] = fma2(s, pack2(d1[2*e], d1[2*e+1]), acc[1][e][1]);
                }
            } else {
                #pragma unroll
                for (int k = 0; k < 3; k++) {
                    const float* sp = &Sf[((3 + k) * 16 + ntp) * 128 + eoff];
                    #pragma unroll
                    for (int e = 0; e < 2; e++) {
                        ull s = splat2(sp[8 * e]);
                        acc[2+k][e][0] = fma2(s, pack2(d0[2*e], d0[2*e+1]), acc[2+k][e][0]);
                        acc[2+k][e][1] = fma2(s, pack2(d1[2*e], d1[2*e+1]), acc[2+k][e][1]);
                    }
                }
            }
        }
        __syncthreads();   // release buffer b
    }

    // ---- epilogue: scatter-add via vector reds ----
    const int q = lane & 3;
    #pragma unroll
    for (int e = 0; e < 2; e++) {
        const int el = eoff + 8 * e;
        const int eg = e_base + el;
        if (eg >= E) continue;
        float* op = out + (size_t)dsts[el] * 64;
        const float k0 = attr[el * 4 + 1];
        const float k1 = attr[el * 4 + 2];
        const float k2 = attr[el * 4 + 3];

        #pragma unroll
        for (int p = 0; p < 2; p++) {
            float m0a, m0b, ta, tb;
            float a0a, a0b, a1a, a1b, a2a, a2b;
            unpack2(acc[0][e][p], m0a, m0b);
            unpack2(acc[1][e][p], ta, tb);
            unpack2(acc[2][e][p], a0a, a0b);
            unpack2(acc[3][e][p], a1a, a1b);
            unpack2(acc[4][e][p], a2a, a2b);
            const int v = 8 * p + 2 * q;
            red2(op + v, SCALE_OUT * m0a, SCALE_OUT * m0b);
            const int base = 16 + 3 * v;
            red2(op + base,     SCALE_OUT * fmaf(k0, ta, a0a), SCALE_OUT * fmaf(k1, ta, a1a));
            red2(op + base + 2, SCALE_OUT * fmaf(k2, ta, a2a), SCALE_OUT * fmaf(k0, tb, a0b));
            red2(op + base + 4, SCALE_OUT * fmaf(k1, tb, a1b), SCALE_OUT * fmaf(k2, tb, a2b));
        }
    }
}

// ---------- self-connection (initializes all of out) ----------
__global__ void sc_kernel(const float* __restrict__ x,
                          const float* __restrict__ L0,
                          const float* __restrict__ L1,
                          float* __restrict__ out,
                          int Nnodes)
{
    __shared__ float l0[256], l1[256];
    int t = threadIdx.x;
    l0[t] = L0[t];
    l1[t] = L1[t];
    __syncthreads();

    int n = blockIdx.x * blockDim.x + t;
    if (n >= Nnodes) return;

    float xv[64];
    const float4* xr = reinterpret_cast<const float4*>(x + (size_t)n * 64);
    #pragma unroll
    for (int i = 0; i < 16; i++) {
        float4 v = xr[i];
        xv[4 * i + 0] = v.x; xv[4 * i + 1] = v.y;
        xv[4 * i + 2] = v.z; xv[4 * i + 3] = v.w;
    }

    float* orow = out + (size_t)n * 64;
    #pragma unroll
    for (int v = 0; v < 16; v++) {
        float s = 0.f;
        #pragma unroll
        for (int u = 0; u < 16; u++) s += xv[u] * l0[u * 16 + v];
        orow[v] = INV_SQRT_MUL * s;
    }
    #pragma unroll
    for (int v = 0; v < 16; v++) {
        float sk0 = 0.f, sk1 = 0.f, sk2 = 0.f;
        #pragma unroll
        for (int u = 0; u < 16; u++) {
            float L = l1[u * 16 + v];
            sk0 += xv[16 + 3 * u + 0] * L;
            sk1 += xv[16 + 3 * u + 1] * L;
            sk2 += xv[16 + 3 * u + 2] * L;
        }
        orow[16 + 3 * v + 0] = INV_SQRT_MUL * sk0;
        orow[16 + 3 * v + 1] = INV_SQRT_MUL * sk1;
        orow[16 + 3 * v + 2] = INV_SQRT_MUL * sk2;
    }
}

extern "C" void kernel_launch(void* const* d_in, const int* in_sizes, int n_in,
                              void* d_out, int out_size)
{
    const float* x         = (const float*)d_in[0];
    const float* edge_attr = (const float*)d_in[1];
    const float* edge_len  = (const float*)d_in[2];
    const int*   src       = (const int*)d_in[3];
    const int*   dst       = (const int*)d_in[4];
    const float* W1        = (const float*)d_in[5];
    const float* W2        = (const float*)d_in[6];
    const float* L0        = (const float*)d_in[7];
    const float* L1        = (const float*)d_in[8];
    float* out = (float*)d_out;

    const int E = in_sizes[2];
    const int Nnodes = in_sizes[0] / 64;

    cudaFuncSetAttribute(edge_mma_kernel, cudaFuncAttributeMaxDynamicSharedMemorySize, SMEM_BYTES);

    prep_w2<<<256, 256>>>(W2);
    sc_kernel<<<(Nnodes + 255) / 256, 256>>>(x, L0, L1, out, Nnodes);
    edge_mma_kernel<<<(E + TILE_E - 1) / TILE_E, THREADS, SMEM_BYTES>>>(
        x, edge_attr, edge_len, src, dst, W1, out, E);
}

// round 8
// speedup vs baseline: 4.7121x; 1.7665x over previous
#include <cuda_runtime.h>
#include <cuda_fp16.h>
#include <cstdint>

typedef unsigned int u32;
typedef unsigned long long u64;

#define THREADS 256
#define TILE_E 128

#define INV_SQRT3 0.5773502691896258f
#define INV_SQRT8 0.35355339059327373f
#define SCALE_OUT 0.022097086912079608f   // PATH_ALPHA / sqrt(HIDDEN)
#define INV_SQRT_MUL 0.25f

// ---- shared memory byte offsets (from 1024-aligned base) ----
#define OFF_A    0          // 128 rows x 128B (64 f16), swizzled  (16KB)
#define OFF_B    16384      // 1 buffer: 256 rows x 128B (32KB)
#define OFF_S    49152      // float[6][16][128] = 48KB
#define OFF_RAD  98304      // float[128][8]
#define OFF_W1   102400     // float[512]
#define OFF_ATTR 104448     // float[128][4]
#define OFF_DST  106496     // int[128]
#define OFF_SRC  107008     // int[128]
#define SMEM_BYTES (107520 + 1024)

// W2 pre-transposed f16: [m(1024)][k(64)]  (B^T row-major)
__device__ __align__(16) __half g_w2t[1024 * 64];

// ---------------- PTX helpers ----------------
__device__ __forceinline__ u32 smem_u32(const void* p) {
    u32 a;
    asm("{ .reg .u64 t; cvta.to.shared.u64 t, %1; cvt.u32.u64 %0, t; }"
        : "=r"(a) : "l"(p));
    return a;
}
__device__ __forceinline__ u32 swz(u32 row, u32 kb) {
    return row * 128 + (kb ^ ((row & 7) << 4));
}
__device__ __forceinline__ void ldsm4(u32* r, u32 addr) {
    asm volatile("ldmatrix.sync.aligned.m8n8.x4.shared.b16 {%0,%1,%2,%3}, [%4];"
                 : "=r"(r[0]), "=r"(r[1]), "=r"(r[2]), "=r"(r[3]) : "r"(addr));
}
__device__ __forceinline__ void mma16816(float* d, const u32* a, const u32* b) {
    asm volatile("mma.sync.aligned.m16n8k16.row.col.f32.f16.f16.f32 "
                 "{%0,%1,%2,%3}, {%4,%5,%6,%7}, {%8,%9}, {%0,%1,%2,%3};"
                 : "+f"(d[0]), "+f"(d[1]), "+f"(d[2]), "+f"(d[3])
                 : "r"(a[0]), "r"(a[1]), "r"(a[2]), "r"(a[3]),
                   "r"(b[0]), "r"(b[1]));
}
__device__ __forceinline__ void cp16(u32 dst, const void* src) {
    asm volatile("cp.async.cg.shared.global [%0], [%1], 16;" :: "r"(dst), "l"(src));
}
#define CP_COMMIT() asm volatile("cp.async.commit_group;" ::: "memory")
#define CP_WAIT0()  asm volatile("cp.async.wait_group 0;" ::: "memory")

typedef unsigned long long ull;
__device__ __forceinline__ ull pack2(float lo, float hi) {
    ull r; asm("mov.b64 %0, {%1, %2};" : "=l"(r) : "f"(lo), "f"(hi)); return r;
}
__device__ __forceinline__ ull splat2(float v) { return pack2(v, v); }
__device__ __forceinline__ void unpack2(ull v, float& lo, float& hi) {
    asm("mov.b64 {%0, %1}, %2;" : "=f"(lo), "=f"(hi) : "l"(v));
}
__device__ __forceinline__ ull fma2(ull a, ull b, ull c) {
    ull d; asm("fma.rn.f32x2 %0, %1, %2, %3;" : "=l"(d) : "l"(a), "l"(b), "l"(c)); return d;
}
__device__ __forceinline__ void red2(float* p, float a, float b) {
    asm volatile("red.global.add.v2.f32 [%0], {%1,%2};" :: "l"(p), "f"(a), "f"(b) : "memory");
}

// ---------------- prep: transpose W2 -> f16 ----------------
__global__ void prep_w2(const float* __restrict__ W2) {
    int i = blockIdx.x * 256 + threadIdx.x;   // over 64*1024
    float v = W2[i];
    int k = i >> 10, m = i & 1023;
    g_w2t[m * 64 + k] = __float2half(v);
}

// ---------------- B staging: block b -> swizzled SMEM buffer ----------------
__device__ __forceinline__ void prefetchB(u32 sbase, int b, int tid) {
    const char* g = (const char*)g_w2t + b * 32768;
    u32 d = sbase + OFF_B;
    #pragma unroll
    for (int it = 0; it < 8; it++) {
        int i = tid + it * THREADS;           // 0..2047 16B chunks
        u32 row = (u32)(i >> 3), c16 = (u32)((i & 7) * 16);
        cp16(d + swz(row, c16), g + (size_t)i * 16);
    }
    CP_COMMIT();
}

// load one 16x16 (n-rows x k) B fragment group: dst[kt 0..3][2]
__device__ __forceinline__ void ldB(u32 dst[4][2], u32 base, u32 nrow,
                                    u32 brow_r, u32 bkb_g) {
    #pragma unroll
    for (int h = 0; h < 2; h++) {
        u32 t[4];
        ldsm4(t, base + swz(nrow + brow_r, (u32)h * 64 + bkb_g));
        dst[2*h][0] = t[0]; dst[2*h][1] = t[1];
        dst[2*h+1][0] = t[2]; dst[2*h+1][1] = t[3];
    }
}

// ---------------- main edge kernel ----------------
__global__ void __launch_bounds__(THREADS, 2)
edge_mma_kernel(const float* __restrict__ x,
                const float* __restrict__ edge_attr,
                const float* __restrict__ edge_len,
                const int* __restrict__ src,
                const int* __restrict__ dst,
                const float* __restrict__ W1,
                float* __restrict__ out,
                int E)
{
    extern __shared__ char smem_raw[];
    char* smem = (char*)((((size_t)smem_raw) + 1023) & ~(size_t)1023);
    const u32 sbase = smem_u32(smem);
    const int tid = threadIdx.x;
    const int wid = tid >> 5;
    const int lane = tid & 31;
    const int e_base = blockIdx.x * TILE_E;

    // start streaming B block 0 immediately
    prefetchB(sbase, 0, tid);

    float* w1s  = (float*)(smem + OFF_W1);
    float* attr = (float*)(smem + OFF_ATTR);
    int*   dsts = (int*)(smem + OFF_DST);
    int*   srcs = (int*)(smem + OFF_SRC);
    float* rad  = (float*)(smem + OFF_RAD);
    float* Sf   = (float*)(smem + OFF_S);

    for (int i = tid; i < 512; i += THREADS) w1s[i] = W1[i];

    if (tid < TILE_E) {
        int e = e_base + tid;
        int ec = e < E ? e : E - 1;      // clamp; epilogue predicates
        srcs[tid] = src[ec];
        dsts[tid] = dst[ec];
        float len = edge_len[ec];
        float4 a = reinterpret_cast<const float4*>(edge_attr)[ec];
        attr[tid * 4 + 0] = a.x; attr[tid * 4 + 1] = a.y;
        attr[tid * 4 + 2] = a.z; attr[tid * 4 + 3] = a.w;
        #pragma unroll
        for (int r = 0; r < 8; r++) {
            float d = len - (5.0f / 7.0f) * (float)r;
            rad[tid * 8 + r] = __expf(-0.5f * d * d);
        }
    }
    __syncthreads();

    // h = silu(radial @ W1 / sqrt(8)) -> f16 A tile (swizzled rows of 128B)
    for (int i = tid; i < TILE_E * 64; i += THREADS) {
        int e = i >> 6, j = i & 63;
        float s = 0.f;
        #pragma unroll
        for (int r = 0; r < 8; r++) s += rad[e * 8 + r] * w1s[r * 64 + j];
        s *= INV_SQRT8;
        float hv = s / (1.0f + __expf(-s));
        *reinterpret_cast<__half*>(smem + OFF_A + swz((u32)e, (u32)(j * 2))) =
            __float2half(hv);
    }

    // per-edge s vectors: S[fam][u][e]
    for (int i = tid; i < TILE_E * 16; i += THREADS) {
        int e = i & 127, u = i >> 7;
        int row = srcs[e] * 64;
        float x0  = x[row + u];
        float x10 = x[row + 16 + 3 * u + 0];
        float x11 = x[row + 16 + 3 * u + 1];
        float x12 = x[row + 16 + 3 * u + 2];
        float sh0 = attr[e * 4 + 0];
        float a1 = attr[e * 4 + 1], a2 = attr[e * 4 + 2], a3 = attr[e * 4 + 3];
        Sf[(0 * 16 + u) * 128 + e] = sh0 * x0;
        Sf[(1 * 16 + u) * 128 + e] = INV_SQRT3 * (x10 * a1 + x11 * a2 + x12 * a3);
        Sf[(2 * 16 + u) * 128 + e] = x0;
        Sf[(3 * 16 + u) * 128 + e] = sh0 * x10;
        Sf[(4 * 16 + u) * 128 + e] = sh0 * x11;
        Sf[(5 * 16 + u) * 128 + e] = sh0 * x12;
    }
    __syncthreads();   // A tile + S ready

    // ---- preload A fragments (4 k-tiles) ----
    u32 Af[4][4];
    {
        u32 grp = (u32)(lane >> 3), r = (u32)(lane & 7);
        u32 arow = (u32)(wid * 16) + r + (grp & 1) * 8;
        u32 akb  = (grp >> 1) * 16;
        #pragma unroll
        for (int kt = 0; kt < 4; kt++)
            ldsm4(Af[kt], sbase + OFF_A + swz(arow, akb + (u32)kt * 32));
    }

    // accumulators: [fam 0..4][edge 0..1][vpair 0..1] as f32x2
    ull acc[5][2][2];
    #pragma unroll
    for (int f = 0; f < 5; f++)
        #pragma unroll
        for (int e = 0; e < 2; e++) { acc[f][e][0] = 0ull; acc[f][e][1] = 0ull; }

    const int eoff = wid * 16 + (lane >> 2);   // e0 local index
    const u32 brow_r = (u32)(lane & 7);
    const u32 bkb_g  = (u32)((lane >> 3) * 16);
    const u32 bbase  = sbase + OFF_B;

    #pragma unroll
    for (int b = 0; b < 4; b++) {
        CP_WAIT0();
        __syncthreads();   // B[b] visible to all

        // 8 steps; each handles u-pair (2*ntq, 2*ntq+1) with 4 independent chains
        #pragma unroll 2
        for (int ntq = 0; ntq < 8; ntq++) {
            u32 Bf[4][4][2];
            #pragma unroll
            for (int ch = 0; ch < 4; ch++)
                ldB(Bf[ch], bbase, (u32)(32 * ntq + 8 * ch), brow_r, bkb_g);

            float c[4][4];
            #pragma unroll
            for (int ch = 0; ch < 4; ch++)
                { c[ch][0] = 0.f; c[ch][1] = 0.f; c[ch][2] = 0.f; c[ch][3] = 0.f; }
            #pragma unroll
            for (int kt = 0; kt < 4; kt++)
                #pragma unroll
                for (int ch = 0; ch < 4; ch++)
                    mma16816(c[ch], Af[kt], Bf[ch][kt]);

            #pragma unroll
            for (int uu = 0; uu < 2; uu++) {
                const int u = 2 * ntq + uu;
                const float* d0 = c[2 * uu];       // v 0..7
                const float* d1 = c[2 * uu + 1];   // v 8..15
                if (b == 0 || b == 1) {
                    const float* sp = &Sf[(b * 16 + u) * 128 + eoff];
                    #pragma unroll
                    for (int e = 0; e < 2; e++) {
                        ull s = splat2(sp[8 * e]);
                        acc[0][e][0] = fma2(s, pack2(d0[2*e], d0[2*e+1]), acc[0][e][0]);
                        acc[0][e][1] = fma2(s, pack2(d1[2*e], d1[2*e+1]), acc[0][e][1]);
                    }
                } else if (b == 2) {
                    const float* sp = &Sf[(2 * 16 + u) * 128 + eoff];
                    #pragma unroll
                    for (int e = 0; e < 2; e++) {
                        ull s = splat2(sp[8 * e]);
                        acc[1][e][0] = fma2(s, pack2(d0[2*e], d0[2*e+1]), acc[1][e][0]);
                        acc[1][e][1] = fma2(s, pack2(d1[2*e], d1[2*e+1]), acc[1][e][1]);
                    }
                } else {
                    #pragma unroll
                    for (int k = 0; k < 3; k++) {
                        const float* sp = &Sf[((3 + k) * 16 + u) * 128 + eoff];
                        #pragma unroll
                        for (int e = 0; e < 2; e++) {
                            ull s = splat2(sp[8 * e]);
                            acc[2+k][e][0] = fma2(s, pack2(d0[2*e], d0[2*e+1]), acc[2+k][e][0]);
                            acc[2+k][e][1] = fma2(s, pack2(d1[2*e], d1[2*e+1]), acc[2+k][e][1]);
                        }
                    }
                }
            }
        }
        __syncthreads();   // all warps done with B[b]
        if (b < 3) prefetchB(sbase, b + 1, tid);
    }

    // ---- epilogue: scatter-add via vector reds ----
    const int q = lane & 3;
    #pragma unroll
    for (int e = 0; e < 2; e++) {
        const int el = eoff + 8 * e;
        const int eg = e_base + el;
        if (eg >= E) continue;
        float* op = out + (size_t)dsts[el] * 64;
        const float k0 = attr[el * 4 + 1];
        const float k1 = attr[el * 4 + 2];
        const float k2 = attr[el * 4 + 3];

        #pragma unroll
        for (int p = 0; p < 2; p++) {
            float m0a, m0b, ta, tb;
            float a0a, a0b, a1a, a1b, a2a, a2b;
            unpack2(acc[0][e][p], m0a, m0b);
            unpack2(acc[1][e][p], ta, tb);
            unpack2(acc[2][e][p], a0a, a0b);
            unpack2(acc[3][e][p], a1a, a1b);
            unpack2(acc[4][e][p], a2a, a2b);
            const int v = 8 * p + 2 * q;
            red2(op + v, SCALE_OUT * m0a, SCALE_OUT * m0b);
            const int base = 16 + 3 * v;
            red2(op + base,     SCALE_OUT * fmaf(k0, ta, a0a), SCALE_OUT * fmaf(k1, ta, a1a));
            red2(op + base + 2, SCALE_OUT * fmaf(k2, ta, a2a), SCALE_OUT * fmaf(k0, tb, a0b));
            red2(op + base + 4, SCALE_OUT * fmaf(k1, tb, a1b), SCALE_OUT * fmaf(k2, tb, a2b));
        }
    }
}

// ---------- self-connection (initializes all of out) ----------
__global__ void sc_kernel(const float* __restrict__ x,
                          const float* __restrict__ L0,
                          const float* __restrict__ L1,
                          float* __restrict__ out,
                          int Nnodes)
{
    __shared__ float l0[256], l1[256];
    int t = threadIdx.x;
    l0[t] = L0[t];
    l1[t] = L1[t];
    __syncthreads();

    int n = blockIdx.x * blockDim.x + t;
    if (n >= Nnodes) return;

    float xv[64];
    const float4* xr = reinterpret_cast<const float4*>(x + (size_t)n * 64);
    #pragma unroll
    for (int i = 0; i < 16; i++) {
        float4 v = xr[i];
        xv[4 * i + 0] = v.x; xv[4 * i + 1] = v.y;
        xv[4 * i + 2] = v.z; xv[4 * i + 3] = v.w;
    }

    float* orow = out + (size_t)n * 64;
    #pragma unroll
    for (int v = 0; v < 16; v++) {
        float s = 0.f;
        #pragma unroll
        for (int u = 0; u < 16; u++) s += xv[u] * l0[u * 16 + v];
        orow[v] = INV_SQRT_MUL * s;
    }
    #pragma unroll
    for (int v = 0; v < 16; v++) {
        float sk0 = 0.f, sk1 = 0.f, sk2 = 0.f;
        #pragma unroll
        for (int u = 0; u < 16; u++) {
            float L = l1[u * 16 + v];
            sk0 += xv[16 + 3 * u + 0] * L;
            sk1 += xv[16 + 3 * u + 1] * L;
            sk2 += xv[16 + 3 * u + 2] * L;
        }
        orow[16 + 3 * v + 0] = INV_SQRT_MUL * sk0;
        orow[16 + 3 * v + 1] = INV_SQRT_MUL * sk1;
        orow[16 + 3 * v + 2] = INV_SQRT_MUL * sk2;
    }
}

extern "C" void kernel_launch(void* const* d_in, const int* in_sizes, int n_in,
                              void* d_out, int out_size)
{
    const float* x         = (const float*)d_in[0];
    const float* edge_attr = (const float*)d_in[1];
    const float* edge_len  = (const float*)d_in[2];
    const int*   src       = (const int*)d_in[3];
    const int*   dst       = (const int*)d_in[4];
    const float* W1        = (const float*)d_in[5];
    const float* W2        = (const float*)d_in[6];
    const float* L0        = (const float*)d_in[7];
    const float* L1        = (const float*)d_in[8];
    float* out = (float*)d_out;

    const int E = in_sizes[2];
    const int Nnodes = in_sizes[0] / 64;

    cudaFuncSetAttribute(edge_mma_kernel, cudaFuncAttributeMaxDynamicSharedMemorySize, SMEM_BYTES);

    prep_w2<<<256, 256>>>(W2);
    sc_kernel<<<(Nnodes + 255) / 256, 256>>>(x, L0, L1, out, Nnodes);
    edge_mma_kernel<<<(E + TILE_E - 1) / TILE_E, THREADS, SMEM_BYTES>>>(
        x, edge_attr, edge_len, src, dst, W1, out, E);
}

// round 11
// speedup vs baseline: 5.8621x; 1.2441x over previous
#include <cuda_runtime.h>
#include <cuda_fp16.h>
#include <cstdint>

typedef unsigned int u32;
typedef unsigned long long u64;

#define THREADS 256
#define TILE_E 128

#define INV_SQRT3 0.5773502691896258f
#define INV_SQRT8 0.35355339059327373f
#define SCALE_OUT 0.022097086912079608f   // PATH_ALPHA / sqrt(HIDDEN)
#define INV_SQRT_MUL 0.25f

// ---- shared memory byte offsets (from 1024-aligned base) ----
#define OFF_A    0          // 128 rows x 128B (64 f16), swizzled  (16KB)
#define OFF_B    16384      // 32KB: x-row staging first, then B blocks
#define OFF_S    49152      // float[6][128][17] = 52224
#define OFF_RAD  101376     // float[128][8]
#define OFF_W1   105472     // float[512]
#define OFF_ATTR 107520     // float[128][4]
#define OFF_DST  109568     // int[128]
#define OFF_SRC  110080     // int[128]
#define SMEM_BYTES (110592 + 1024)

#define SE_STR 17
#define SF_STR 2176        // 128*17

// W2 pre-transposed f16: [m(1024)][k(64)]  (B^T row-major)
__device__ __align__(16) __half g_w2t[1024 * 64];

// ---------------- PTX helpers ----------------
__device__ __forceinline__ u32 smem_u32(const void* p) {
    u32 a;
    asm("{ .reg .u64 t; cvta.to.shared.u64 t, %1; cvt.u32.u64 %0, t; }"
        : "=r"(a) : "l"(p));
    return a;
}
__device__ __forceinline__ u32 swz(u32 row, u32 kb) {
    return row * 128 + (kb ^ ((row & 7) << 4));
}
__device__ __forceinline__ void ldsm4(u32* r, u32 addr) {
    asm volatile("ldmatrix.sync.aligned.m8n8.x4.shared.b16 {%0,%1,%2,%3}, [%4];"
                 : "=r"(r[0]), "=r"(r[1]), "=r"(r[2]), "=r"(r[3]) : "r"(addr));
}
__device__ __forceinline__ void mma16816(float* d, const u32* a, const u32* b) {
    asm volatile("mma.sync.aligned.m16n8k16.row.col.f32.f16.f16.f32 "
                 "{%0,%1,%2,%3}, {%4,%5,%6,%7}, {%8,%9}, {%0,%1,%2,%3};"
                 : "+f"(d[0]), "+f"(d[1]), "+f"(d[2]), "+f"(d[3])
                 : "r"(a[0]), "r"(a[1]), "r"(a[2]), "r"(a[3]),
                   "r"(b[0]), "r"(b[1]));
}
__device__ __forceinline__ void cp16(u32 dst, const void* src) {
    asm volatile("cp.async.cg.shared.global [%0], [%1], 16;" :: "r"(dst), "l"(src));
}
#define CP_COMMIT() asm volatile("cp.async.commit_group;" ::: "memory")
#define CP_WAIT0()  asm volatile("cp.async.wait_group 0;" ::: "memory")

typedef unsigned long long ull;
__device__ __forceinline__ ull pack2(float lo, float hi) {
    ull r; asm("mov.b64 %0, {%1, %2};" : "=l"(r) : "f"(lo), "f"(hi)); return r;
}
__device__ __forceinline__ ull splat2(float v) { return pack2(v, v); }
__device__ __forceinline__ void unpack2(ull v, float& lo, float& hi) {
    asm("mov.b64 {%0, %1}, %2;" : "=f"(lo), "=f"(hi) : "l"(v));
}
__device__ __forceinline__ ull fma2(ull a, ull b, ull c) {
    ull d; asm("fma.rn.f32x2 %0, %1, %2, %3;" : "=l"(d) : "l"(a), "l"(b), "l"(c)); return d;
}
__device__ __forceinline__ void red2(float* p, float a, float b) {
    asm volatile("red.global.add.v2.f32 [%0], {%1,%2};" :: "l"(p), "f"(a), "f"(b) : "memory");
}

// ---------------- prep: transpose W2 -> f16 ----------------
__global__ void prep_w2(const float* __restrict__ W2) {
    int i = blockIdx.x * 256 + threadIdx.x;   // over 64*1024
    float v = W2[i];
    int k = i >> 10, m = i & 1023;
    g_w2t[m * 64 + k] = __float2half(v);
}

// ---------------- B staging: block b -> swizzled SMEM buffer ----------------
__device__ __forceinline__ void prefetchB(u32 sbase, int b, int tid) {
    const char* g = (const char*)g_w2t + b * 32768;
    u32 d = sbase + OFF_B;
    #pragma unroll
    for (int it = 0; it < 8; it++) {
        int i = tid + it * THREADS;           // 0..2047 16B chunks
        u32 row = (u32)(i >> 3), c16 = (u32)((i & 7) * 16);
        cp16(d + swz(row, c16), g + (size_t)i * 16);
    }
    CP_COMMIT();
}

// load one 16x16 (n-rows x k) B fragment group: dst[kt 0..3][2]
__device__ __forceinline__ void ldB(u32 dst[4][2], u32 base, u32 nrow,
                                    u32 brow_r, u32 bkb_g) {
    #pragma unroll
    for (int h = 0; h < 2; h++) {
        u32 t[4];
        ldsm4(t, base + swz(nrow + brow_r, (u32)h * 64 + bkb_g));
        dst[2*h][0] = t[0]; dst[2*h][1] = t[1];
        dst[2*h+1][0] = t[2]; dst[2*h+1][1] = t[3];
    }
}

// ---------------- main edge kernel ----------------
__global__ void __launch_bounds__(THREADS, 2)
edge_mma_kernel(const float* __restrict__ x,
                const float* __restrict__ edge_attr,
                const float* __restrict__ edge_len,
                const int* __restrict__ src,
                const int* __restrict__ dst,
                const float* __restrict__ W1,
                float* __restrict__ out,
                int E)
{
    extern __shared__ char smem_raw[];
    char* smem = (char*)((((size_t)smem_raw) + 1023) & ~(size_t)1023);
    const u32 sbase = smem_u32(smem);
    const int tid = threadIdx.x;
    const int wid = tid >> 5;
    const int lane = tid & 31;
    const int e_base = blockIdx.x * TILE_E;

    float* w1s  = (float*)(smem + OFF_W1);
    float* attr = (float*)(smem + OFF_ATTR);
    int*   dsts = (int*)(smem + OFF_DST);
    int*   srcs = (int*)(smem + OFF_SRC);
    float* rad  = (float*)(smem + OFF_RAD);
    float* Sf   = (float*)(smem + OFF_S);

    for (int i = tid; i < 512; i += THREADS) w1s[i] = W1[i];

    if (tid < TILE_E) {
        int e = e_base + tid;
        int ec = e < E ? e : E - 1;      // clamp; epilogue predicates
        srcs[tid] = src[ec];
        dsts[tid] = dst[ec];
        float len = edge_len[ec];
        float4 a = reinterpret_cast<const float4*>(edge_attr)[ec];
        attr[tid * 4 + 0] = a.x; attr[tid * 4 + 1] = a.y;
        attr[tid * 4 + 2] = a.z; attr[tid * 4 + 3] = a.w;
        #pragma unroll
        for (int r = 0; r < 8; r++) {
            float d = len - (5.0f / 7.0f) * (float)r;
            rad[tid * 8 + r] = __expf(-0.5f * d * d);
        }
    }
    __syncthreads();

    // ---- stage x[src] rows into B region (coalesced cp.async, 256B/row) ----
    {
        u32 braw = sbase + OFF_B;
        #pragma unroll
        for (int it = 0; it < 8; it++) {
            int i = tid + it * THREADS;       // 0..2047
            int e = i >> 4, q = i & 15;
            cp16(braw + (u32)(e * 256 + q * 16),
                 x + (size_t)srcs[e] * 64 + q * 4);
        }
        CP_COMMIT();
    }

    // ---- h = silu(radial @ W1 / sqrt(8)) -> f16 A tile (overlaps x staging) ----
    for (int i = tid; i < TILE_E * 64; i += THREADS) {
        int e = i >> 6, j = i & 63;
        float s = 0.f;
        #pragma unroll
        for (int r = 0; r < 8; r++) s += rad[e * 8 + r] * w1s[r * 64 + j];
        s *= INV_SQRT8;
        float hv = s / (1.0f + __expf(-s));
        *reinterpret_cast<__half*>(smem + OFF_A + swz((u32)e, (u32)(j * 2))) =
            __float2half(hv);
    }

    CP_WAIT0();
    __syncthreads();   // staged x visible

    // ---- per-edge s vectors from SMEM: S[fam][e][17] ----
    {
        const float* raw = (const float*)(smem + OFF_B);
        for (int i = tid; i < TILE_E * 16; i += THREADS) {
            int u = i & 15, e = i >> 4;
            const float* xr = raw + e * 64;
            float x0  = xr[u];
            float x10 = xr[16 + 3 * u + 0];
            float x11 = xr[16 + 3 * u + 1];
            float x12 = xr[16 + 3 * u + 2];
            float sh0 = attr[e * 4 + 0];
            float a1 = attr[e * 4 + 1], a2 = attr[e * 4 + 2], a3 = attr[e * 4 + 3];
            float* sp = Sf + e * SE_STR + u;
            sp[0 * SF_STR] = sh0 * x0;
            sp[1 * SF_STR] = INV_SQRT3 * (x10 * a1 + x11 * a2 + x12 * a3);
            sp[2 * SF_STR] = x0;
            sp[3 * SF_STR] = sh0 * x10;
            sp[4 * SF_STR] = sh0 * x11;
            sp[5 * SF_STR] = sh0 * x12;
        }
    }
    __syncthreads();   // S done; B region free -> start B0

    prefetchB(sbase, 0, tid);

    // ---- preload A fragments (4 k-tiles) ----
    u32 Af[4][4];
    {
        u32 grp = (u32)(lane >> 3), r = (u32)(lane & 7);
        u32 arow = (u32)(wid * 16) + r + (grp & 1) * 8;
        u32 akb  = (grp >> 1) * 16;
        #pragma unroll
        for (int kt = 0; kt < 4; kt++)
            ldsm4(Af[kt], sbase + OFF_A + swz(arow, akb + (u32)kt * 32));
    }

    // accumulators: [fam 0..4][edge 0..1][vpair 0..1] as f32x2
    ull acc[5][2][2];
    #pragma unroll
    for (int f = 0; f < 5; f++)
        #pragma unroll
        for (int e = 0; e < 2; e++) { acc[f][e][0] = 0ull; acc[f][e][1] = 0ull; }

    const int eoff = wid * 16 + (lane >> 2);   // e0 local index
    const u32 brow_r = (u32)(lane & 7);
    const u32 bkb_g  = (u32)((lane >> 3) * 16);
    const u32 bbase  = sbase + OFF_B;

    #pragma unroll
    for (int b = 0; b < 4; b++) {
        CP_WAIT0();
        __syncthreads();   // B[b] visible to all

        // 8 steps; each handles u-pair (2*ntq, 2*ntq+1) with 4 independent chains
        #pragma unroll 2
        for (int ntq = 0; ntq < 8; ntq++) {
            u32 Bf[4][4][2];
            #pragma unroll
            for (int ch = 0; ch < 4; ch++)
                ldB(Bf[ch], bbase, (u32)(32 * ntq + 8 * ch), brow_r, bkb_g);

            float c[4][4];
            #pragma unroll
            for (int ch = 0; ch < 4; ch++)
                { c[ch][0] = 0.f; c[ch][1] = 0.f; c[ch][2] = 0.f; c[ch][3] = 0.f; }
            #pragma unroll
            for (int kt = 0; kt < 4; kt++)
                #pragma unroll
                for (int ch = 0; ch < 4; ch++)
                    mma16816(c[ch], Af[kt], Bf[ch][kt]);

            #pragma unroll
            for (int uu = 0; uu < 2; uu++) {
                const int u = 2 * ntq + uu;
                const float* d0 = c[2 * uu];       // v 0..7
                const float* d1 = c[2 * uu + 1];   // v 8..15
                if (b == 0 || b == 1) {
                    const float* sp = &Sf[b * SF_STR + eoff * SE_STR + u];
                    #pragma unroll
                    for (int e = 0; e < 2; e++) {
                        ull s = splat2(sp[e * 8 * SE_STR]);
                        acc[0][e][0] = fma2(s, pack2(d0[2*e], d0[2*e+1]), acc[0][e][0]);
                        acc[0][e][1] = fma2(s, pack2(d1[2*e], d1[2*e+1]), acc[0][e][1]);
                    }
                } else if (b == 2) {
                    const float* sp = &Sf[2 * SF_STR + eoff * SE_STR + u];
                    #pragma unroll
                    for (int e = 0; e < 2; e++) {
                        ull s = splat2(sp[e * 8 * SE_STR]);
                        acc[1][e][0] = fma2(s, pack2(d0[2*e], d0[2*e+1]), acc[1][e][0]);
                        acc[1][e][1] = fma2(s, pack2(d1[2*e], d1[2*e+1]), acc[1][e][1]);
                    }
                } else {
                    #pragma unroll
                    for (int k = 0; k < 3; k++) {
                        const float* sp = &Sf[(3 + k) * SF_STR + eoff * SE_STR + u];
                        #pragma unroll
                        for (int e = 0; e < 2; e++) {
                            ull s = splat2(sp[e * 8 * SE_STR]);
                            acc[2+k][e][0] = fma2(s, pack2(d0[2*e], d0[2*e+1]), acc[2+k][e][0]);
                            acc[2+k][e][1] = fma2(s, pack2(d1[2*e], d1[2*e+1]), acc[2+k][e][1]);
                        }
                    }
                }
            }
        }
        __syncthreads();   // all warps done with B[b]
        if (b < 3) prefetchB(sbase, b + 1, tid);
    }

    // ---- epilogue: scatter-add via vector reds ----
    const int q = lane & 3;
    #pragma unroll
    for (int e = 0; e < 2; e++) {
        const int el = eoff + 8 * e;
        const int eg = e_base + el;
        if (eg >= E) continue;
        float* op = out + (size_t)dsts[el] * 64;
        const float k0 = attr[el * 4 + 1];
        const float k1 = attr[el * 4 + 2];
        const float k2 = attr[el * 4 + 3];

        #pragma unroll
        for (int p = 0; p < 2; p++) {
            float m0a, m0b, ta, tb;
            float a0a, a0b, a1a, a1b, a2a, a2b;
            unpack2(acc[0][e][p], m0a, m0b);
            unpack2(acc[1][e][p], ta, tb);
            unpack2(acc[2][e][p], a0a, a0b);
            unpack2(acc[3][e][p], a1a, a1b);
            unpack2(acc[4][e][p], a2a, a2b);
            const int v = 8 * p + 2 * q;
            red2(op + v, SCALE_OUT * m0a, SCALE_OUT * m0b);
            const int base = 16 + 3 * v;
            red2(op + base,     SCALE_OUT * fmaf(k0, ta, a0a), SCALE_OUT * fmaf(k1, ta, a1a));
            red2(op + base + 2, SCALE_OUT * fmaf(k2, ta, a2a), SCALE_OUT * fmaf(k0, tb, a0b));
            red2(op + base + 4, SCALE_OUT * fmaf(k1, tb, a1b), SCALE_OUT * fmaf(k2, tb, a2b));
        }
    }
}

// ---------- self-connection (initializes all of out) ----------
__global__ void sc_kernel(const float* __restrict__ x,
                          const float* __restrict__ L0,
                          const float* __restrict__ L1,
                          float* __restrict__ out,
                          int Nnodes)
{
    __shared__ float l0[256], l1[256];
    int t = threadIdx.x;
    l0[t] = L0[t];
    l1[t] = L1[t];
    __syncthreads();

    int n = blockIdx.x * blockDim.x + t;
    if (n >= Nnodes) return;

    float xv[64];
    const float4* xr = reinterpret_cast<const float4*>(x + (size_t)n * 64);
    #pragma unroll
    for (int i = 0; i < 16; i++) {
        float4 v = xr[i];
        xv[4 * i + 0] = v.x; xv[4 * i + 1] = v.y;
        xv[4 * i + 2] = v.z; xv[4 * i + 3] = v.w;
    }

    float* orow = out + (size_t)n * 64;
    #pragma unroll
    for (int v = 0; v < 16; v++) {
        float s = 0.f;
        #pragma unroll
        for (int u = 0; u < 16; u++) s += xv[u] * l0[u * 16 + v];
        orow[v] = INV_SQRT_MUL * s;
    }
    #pragma unroll
    for (int v = 0; v < 16; v++) {
        float sk0 = 0.f, sk1 = 0.f, sk2 = 0.f;
        #pragma unroll
        for (int u = 0; u < 16; u++) {
            float L = l1[u * 16 + v];
            sk0 += xv[16 + 3 * u + 0] * L;
            sk1 += xv[16 + 3 * u + 1] * L;
            sk2 += xv[16 + 3 * u + 2] * L;
        }
        orow[16 + 3 * v + 0] = INV_SQRT_MUL * sk0;
        orow[16 + 3 * v + 1] = INV_SQRT_MUL * sk1;
        orow[16 + 3 * v + 2] = INV_SQRT_MUL * sk2;
    }
}

extern "C" void kernel_launch(void* const* d_in, const int* in_sizes, int n_in,
                              void* d_out, int out_size)
{
    const float* x         = (const float*)d_in[0];
    const float* edge_attr = (const float*)d_in[1];
    const float* edge_len  = (const float*)d_in[2];
    const int*   src       = (const int*)d_in[3];
    const int*   dst       = (const int*)d_in[4];
    const float* W1        = (const float*)d_in[5];
    const float* W2        = (const float*)d_in[6];
    const float* L0        = (const float*)d_in[7];
    const float* L1        = (const float*)d_in[8];
    float* out = (float*)d_out;

    const int E = in_sizes[2];
    const int Nnodes = in_sizes[0] / 64;

    cudaFuncSetAttribute(edge_mma_kernel, cudaFuncAttributeMaxDynamicSharedMemorySize, SMEM_BYTES);

    prep_w2<<<256, 256>>>(W2);
    sc_kernel<<<(Nnodes + 255) / 256, 256>>>(x, L0, L1, out, Nnodes);
    edge_mma_kernel<<<(E + TILE_E - 1) / TILE_E, THREADS, SMEM_BYTES>>>(
        x, edge_attr, edge_len, src, dst, W1, out, E);
}

// round 14
// speedup vs baseline: 6.2852x; 1.0722x over previous
#include <cuda_runtime.h>
#include <cuda_fp16.h>
#include <cstdint>

typedef unsigned int u32;
typedef unsigned long long u64;

#define THREADS 256
#define TILE_E 128

#define INV_SQRT3 0.5773502691896258f
#define INV_SQRT8 0.35355339059327373f
#define SCALE_OUT 0.022097086912079608f   // PATH_ALPHA / sqrt(HIDDEN)
#define INV_SQRT_MUL 0.25f

// ---- shared memory byte offsets (from 1024-aligned base) ----
#define OFF_A    0          // 128 rows x 128B (64 f16), swizzled  (16KB)
#define OFF_B    16384      // 2 x 16KB half-block buffers (32KB total)
#define OFF_S    49152      // float[6][128][17] = 52224
#define OFF_RAD  101376     // float[128][8]
#define OFF_W1   105472     // float[512]
#define OFF_ATTR 107520     // float[128][4]
#define OFF_DST  109568     // int[128]
#define OFF_SRC  110080     // int[128]
#define SMEM_BYTES (110592 + 1024)

#define SE_STR 17
#define SF_STR 2176        // 128*17

// W2 pre-transposed f16: [m(1024)][k(64)]  (B^T row-major)
__device__ __align__(16) __half g_w2t[1024 * 64];

// ---------------- PTX helpers ----------------
__device__ __forceinline__ u32 smem_u32(const void* p) {
    u32 a;
    asm("{ .reg .u64 t; cvta.to.shared.u64 t, %1; cvt.u32.u64 %0, t; }"
        : "=r"(a) : "l"(p));
    return a;
}
__device__ __forceinline__ u32 swz(u32 row, u32 kb) {
    return row * 128 + (kb ^ ((row & 7) << 4));
}
__device__ __forceinline__ void ldsm4(u32* r, u32 addr) {
    asm volatile("ldmatrix.sync.aligned.m8n8.x4.shared.b16 {%0,%1,%2,%3}, [%4];"
                 : "=r"(r[0]), "=r"(r[1]), "=r"(r[2]), "=r"(r[3]) : "r"(addr));
}
__device__ __forceinline__ void mma16816(float* d, const u32* a, const u32* b) {
    asm volatile("mma.sync.aligned.m16n8k16.row.col.f32.f16.f16.f32 "
                 "{%0,%1,%2,%3}, {%4,%5,%6,%7}, {%8,%9}, {%0,%1,%2,%3};"
                 : "+f"(d[0]), "+f"(d[1]), "+f"(d[2]), "+f"(d[3])
                 : "r"(a[0]), "r"(a[1]), "r"(a[2]), "r"(a[3]),
                   "r"(b[0]), "r"(b[1]));
}
__device__ __forceinline__ void cp16(u32 dst, const void* src) {
    asm volatile("cp.async.cg.shared.global [%0], [%1], 16;" :: "r"(dst), "l"(src));
}
#define CP_COMMIT() asm volatile("cp.async.commit_group;" ::: "memory")
#define CP_WAIT0()  asm volatile("cp.async.wait_group 0;" ::: "memory")
#define CP_WAIT1()  asm volatile("cp.async.wait_group 1;" ::: "memory")

typedef unsigned long long ull;
__device__ __forceinline__ ull pack2(float lo, float hi) {
    ull r; asm("mov.b64 %0, {%1, %2};" : "=l"(r) : "f"(lo), "f"(hi)); return r;
}
__device__ __forceinline__ ull splat2(float v) { return pack2(v, v); }
__device__ __forceinline__ void unpack2(ull v, float& lo, float& hi) {
    asm("mov.b64 {%0, %1}, %2;" : "=f"(lo), "=f"(hi) : "l"(v));
}
__device__ __forceinline__ ull fma2(ull a, ull b, ull c) {
    ull d; asm("fma.rn.f32x2 %0, %1, %2, %3;" : "=l"(d) : "l"(a), "l"(b), "l"(c)); return d;
}
__device__ __forceinline__ void red2(float* p, float a, float b) {
    asm volatile("red.global.add.v2.f32 [%0], {%1,%2};" :: "l"(p), "f"(a), "f"(b) : "memory");
}

#define PREP_BLOCKS 64

// ---------------- merged pre-kernel: W2 transpose + self-connection ----------------
__global__ void pre_kernel(const float* __restrict__ W2,
                           const float* __restrict__ x,
                           const float* __restrict__ L0,
                           const float* __restrict__ L1,
                           float* __restrict__ out,
                           int Nnodes)
{
    int blk = blockIdx.x;
    int t = threadIdx.x;
    if (blk < PREP_BLOCKS) {
        // W2 transpose -> f16: one float4 per thread
        int i4 = blk * 256 + t;                 // 0..16383
        float4 v = reinterpret_cast<const float4*>(W2)[i4];
        int i = i4 * 4;
        int k = i >> 10, m = i & 1023;
        g_w2t[(m + 0) * 64 + k] = __float2half(v.x);
        g_w2t[(m + 1) * 64 + k] = __float2half(v.y);
        g_w2t[(m + 2) * 64 + k] = __float2half(v.z);
        g_w2t[(m + 3) * 64 + k] = __float2half(v.w);
        return;
    }

    __shared__ float l0[256], l1[256];
    l0[t] = L0[t];
    l1[t] = L1[t];
    __syncthreads();

    int n = (blk - PREP_BLOCKS) * blockDim.x + t;
    if (n >= Nnodes) return;

    float xv[64];
    const float4* xr = reinterpret_cast<const float4*>(x + (size_t)n * 64);
    #pragma unroll
    for (int i = 0; i < 16; i++) {
        float4 v = xr[i];
        xv[4 * i + 0] = v.x; xv[4 * i + 1] = v.y;
        xv[4 * i + 2] = v.z; xv[4 * i + 3] = v.w;
    }

    float* orow = out + (size_t)n * 64;
    #pragma unroll
    for (int v = 0; v < 16; v++) {
        float s = 0.f;
        #pragma unroll
        for (int u = 0; u < 16; u++) s += xv[u] * l0[u * 16 + v];
        orow[v] = INV_SQRT_MUL * s;
    }
    #pragma unroll
    for (int v = 0; v < 16; v++) {
        float sk0 = 0.f, sk1 = 0.f, sk2 = 0.f;
        #pragma unroll
        for (int u = 0; u < 16; u++) {
            float L = l1[u * 16 + v];
            sk0 += xv[16 + 3 * u + 0] * L;
            sk1 += xv[16 + 3 * u + 1] * L;
            sk2 += xv[16 + 3 * u + 2] * L;
        }
        orow[16 + 3 * v + 0] = INV_SQRT_MUL * sk0;
        orow[16 + 3 * v + 1] = INV_SQRT_MUL * sk1;
        orow[16 + 3 * v + 2] = INV_SQRT_MUL * sk2;
    }
}

// ---------------- B half staging: phase ph (0..7) -> buffer ph&1 ----------------
__device__ __forceinline__ void prefetchBH(u32 sbase, int ph, int tid) {
    const char* g = (const char*)g_w2t + (size_t)ph * 16384;
    u32 d = sbase + OFF_B + (u32)((ph & 1) * 16384);
    #pragma unroll
    for (int it = 0; it < 4; it++) {
        int i = tid + it * THREADS;           // 0..1023 16B chunks
        u32 row = (u32)(i >> 3), c16 = (u32)((i & 7) * 16);
        cp16(d + swz(row, c16), g + (size_t)i * 16);
    }
    CP_COMMIT();
}

// load one 16x16 (n-rows x k) B fragment group: dst[kt 0..3][2]
__device__ __forceinline__ void ldB(u32 dst[4][2], u32 base, u32 nrow,
                                    u32 brow_r, u32 bkb_g) {
    #pragma unroll
    for (int h = 0; h < 2; h++) {
        u32 t[4];
        ldsm4(t, base + swz(nrow + brow_r, (u32)h * 64 + bkb_g));
        dst[2*h][0] = t[0]; dst[2*h][1] = t[1];
        dst[2*h+1][0] = t[2]; dst[2*h+1][1] = t[3];
    }
}

// ---------------- main edge kernel ----------------
__global__ void __launch_bounds__(THREADS, 2)
edge_mma_kernel(const float* __restrict__ x,
                const float* __restrict__ edge_attr,
                const float* __restrict__ edge_len,
                const int* __restrict__ src,
                const int* __restrict__ dst,
                const float* __restrict__ W1,
                float* __restrict__ out,
                int E)
{
    extern __shared__ char smem_raw[];
    char* smem = (char*)((((size_t)smem_raw) + 1023) & ~(size_t)1023);
    const u32 sbase = smem_u32(smem);
    const int tid = threadIdx.x;
    const int wid = tid >> 5;
    const int lane = tid & 31;
    const int e_base = blockIdx.x * TILE_E;

    float* w1s  = (float*)(smem + OFF_W1);
    float* attr = (float*)(smem + OFF_ATTR);
    int*   dsts = (int*)(smem + OFF_DST);
    int*   srcs = (int*)(smem + OFF_SRC);
    float* rad  = (float*)(smem + OFF_RAD);
    float* Sf   = (float*)(smem + OFF_S);

    for (int i = tid; i < 512; i += THREADS) w1s[i] = W1[i];

    if (tid < TILE_E) {
        int e = e_base + tid;
        int ec = e < E ? e : E - 1;      // clamp; epilogue predicates
        srcs[tid] = src[ec];
        dsts[tid] = dst[ec];
        float len = edge_len[ec];
        float4 a = reinterpret_cast<const float4*>(edge_attr)[ec];
        attr[tid * 4 + 0] = a.x; attr[tid * 4 + 1] = a.y;
        attr[tid * 4 + 2] = a.z; attr[tid * 4 + 3] = a.w;
        #pragma unroll
        for (int r = 0; r < 8; r++) {
            float d = len - (5.0f / 7.0f) * (float)r;
            rad[tid * 8 + r] = __expf(-0.5f * d * d);
        }
    }
    __syncthreads();

    const u32 xstage = sbase + OFF_B + 16384;   // buffer 1 doubles as x staging

    // G1: stage x rows for edges 0..63 (4 chunks/thread, coalesced)
    #pragma unroll
    for (int it = 0; it < 4; it++) {
        int i = tid + it * THREADS;       // 0..1023
        int el = i >> 4, q = i & 15;
        cp16(xstage + (u32)(el * 256 + q * 16), x + (size_t)srcs[el] * 64 + q * 4);
    }
    CP_COMMIT();
    // G2: B block0 half0 -> buffer 0 (streams during prologue)
    prefetchBH(sbase, 0, tid);

    // ---- h = silu(radial @ W1 / sqrt(8)) -> f16 A tile (overlaps staging) ----
    for (int i = tid; i < TILE_E * 64; i += THREADS) {
        int e = i >> 6, j = i & 63;
        float s = 0.f;
        #pragma unroll
        for (int r = 0; r < 8; r++) s += rad[e * 8 + r] * w1s[r * 64 + j];
        s *= INV_SQRT8;
        float hv = s / (1.0f + __expf(-s));
        *reinterpret_cast<__half*>(smem + OFF_A + swz((u32)e, (u32)(j * 2))) =
            __float2half(hv);
    }

    CP_WAIT1();          // G1 (x pass 1) done; G2 may still stream
    __syncthreads();

    // ---- S build pass 1 (edges 0..63) ----
    {
        const float* raw = (const float*)(smem + OFF_B + 16384);
        #pragma unroll
        for (int it = 0; it < 4; it++) {
            int i = tid + it * THREADS;
            int u = i & 15, el = i >> 4;
            const float* xr = raw + el * 64;
            float x0  = xr[u];
            float x10 = xr[16 + 3 * u + 0];
            float x11 = xr[16 + 3 * u + 1];
            float x12 = xr[16 + 3 * u + 2];
            float sh0 = attr[el * 4 + 0];
            float a1 = attr[el * 4 + 1], a2 = attr[el * 4 + 2], a3 = attr[el * 4 + 3];
            float* sp = Sf + el * SE_STR + u;
            sp[0 * SF_STR] = sh0 * x0;
            sp[1 * SF_STR] = INV_SQRT3 * (x10 * a1 + x11 * a2 + x12 * a3);
            sp[2 * SF_STR] = x0;
            sp[3 * SF_STR] = sh0 * x10;
            sp[4 * SF_STR] = sh0 * x11;
            sp[5 * SF_STR] = sh0 * x12;
        }
    }
    __syncthreads();     // all reads of staged pass-1 rows complete

    // G3: stage x rows for edges 64..127
    #pragma unroll
    for (int it = 0; it < 4; it++) {
        int i = tid + it * THREADS;
        int el = i >> 4, q = i & 15;
        cp16(xstage + (u32)(el * 256 + q * 16), x + (size_t)srcs[64 + el] * 64 + q * 4);
    }
    CP_COMMIT();
    CP_WAIT0();          // G2 + G3 done
    __syncthreads();

    // ---- S build pass 2 (edges 64..127) ----
    {
        const float* raw = (const float*)(smem + OFF_B + 16384);
        #pragma unroll
        for (int it = 0; it < 4; it++) {
            int i = tid + it * THREADS;
            int u = i & 15, el = i >> 4;
            int e = 64 + el;
            const float* xr = raw + el * 64;
            float x0  = xr[u];
            float x10 = xr[16 + 3 * u + 0];
            float x11 = xr[16 + 3 * u + 1];
            float x12 = xr[16 + 3 * u + 2];
            float sh0 = attr[e * 4 + 0];
            float a1 = attr[e * 4 + 1], a2 = attr[e * 4 + 2], a3 = attr[e * 4 + 3];
            float* sp = Sf + e * SE_STR + u;
            sp[0 * SF_STR] = sh0 * x0;
            sp[1 * SF_STR] = INV_SQRT3 * (x10 * a1 + x11 * a2 + x12 * a3);
            sp[2 * SF_STR] = x0;
            sp[3 * SF_STR] = sh0 * x10;
            sp[4 * SF_STR] = sh0 * x11;
            sp[5 * SF_STR] = sh0 * x12;
        }
    }
    __syncthreads();     // buffer 1 free; S complete

    prefetchBH(sbase, 1, tid);    // B block0 half1 -> buffer 1

    // ---- preload A fragments (4 k-tiles) ----
    u32 Af[4][4];
    {
        u32 grp = (u32)(lane >> 3), r = (u32)(lane & 7);
        u32 arow = (u32)(wid * 16) + r + (grp & 1) * 8;
        u32 akb  = (grp >> 1) * 16;
        #pragma unroll
        for (int kt = 0; kt < 4; kt++)
            ldsm4(Af[kt], sbase + OFF_A + swz(arow, akb + (u32)kt * 32));
    }

    // accumulators: [fam 0..4][edge 0..1][vpair 0..1] as f32x2
    ull acc[5][2][2];
    #pragma unroll
    for (int f = 0; f < 5; f++)
        #pragma unroll
        for (int e = 0; e < 2; e++) { acc[f][e][0] = 0ull; acc[f][e][1] = 0ull; }

    const int eoff = wid * 16 + (lane >> 2);   // e0 local index
    const u32 brow_r = (u32)(lane & 7);
    const u32 bkb_g  = (u32)((lane >> 3) * 16);

    // ---- 8-phase pipelined mainloop (phase = block*2 + half, 128 n-rows each) ----
    #pragma unroll
    for (int p = 0; p < 8; p++) {
        if (p >= 1) {
            if (p == 7) { CP_WAIT0(); } else { CP_WAIT1(); }
            __syncthreads();   // buffer (p&1) ready & visible
        }
        const int b = p >> 1;
        const int half = p & 1;
        const u32 bbase = sbase + OFF_B + (u32)(half * 16384);

        #pragma unroll
        for (int ntq = 0; ntq < 4; ntq++) {
            u32 Bf[4][4][2];
            #pragma unroll
            for (int ch = 0; ch < 4; ch++)
                ldB(Bf[ch], bbase, (u32)(32 * ntq + 8 * ch), brow_r, bkb_g);

            float c[4][4];
            #pragma unroll
            for (int ch = 0; ch < 4; ch++)
                { c[ch][0] = 0.f; c[ch][1] = 0.f; c[ch][2] = 0.f; c[ch][3] = 0.f; }
            #pragma unroll
            for (int kt = 0; kt < 4; kt++)
                #pragma unroll
                for (int ch = 0; ch < 4; ch++)
                    mma16816(c[ch], Af[kt], Bf[ch][kt]);

            #pragma unroll
            for (int uu = 0; uu < 2; uu++) {
                const int u = half * 8 + 2 * ntq + uu;
                const float* d0 = c[2 * uu];       // v 0..7
                const float* d1 = c[2 * uu + 1];   // v 8..15
                if (b == 0 || b == 1) {
                    const float* sp = &Sf[b * SF_STR + eoff * SE_STR + u];
                    #pragma unroll
                    for (int e = 0; e < 2; e++) {
                        ull s = splat2(sp[e * 8 * SE_STR]);
                        acc[0][e][0] = fma2(s, pack2(d0[2*e], d0[2*e+1]), acc[0][e][0]);
                        acc[0][e][1] = fma2(s, pack2(d1[2*e], d1[2*e+1]), acc[0][e][1]);
                    }
                } else if (b == 2) {
                    const float* sp = &Sf[2 * SF_STR + eoff * SE_STR + u];
                    #pragma unroll
                    for (int e = 0; e < 2; e++) {
                        ull s = splat2(sp[e * 8 * SE_STR]);
                        acc[1][e][0] = fma2(s, pack2(d0[2*e], d0[2*e+1]), acc[1][e][0]);
                        acc[1][e][1] = fma2(s, pack2(d1[2*e], d1[2*e+1]), acc[1][e][1]);
                    }
                } else {
                    #pragma unroll
                    for (int k = 0; k < 3; k++) {
                        const float* sp = &Sf[(3 + k) * SF_STR + eoff * SE_STR + u];
                        #pragma unroll
                        for (int e = 0; e < 2; e++) {
                            ull s = splat2(sp[e * 8 * SE_STR]);
                            acc[2+k][e][0] = fma2(s, pack2(d0[2*e], d0[2*e+1]), acc[2+k][e][0]);
                            acc[2+k][e][1] = fma2(s, pack2(d1[2*e], d1[2*e+1]), acc[2+k][e][1]);
                        }
                    }
                }
            }
        }

        if (p < 6) {
            __syncthreads();              // all warps done reading buffer (p&1)
            prefetchBH(sbase, p + 2, tid);
        }
    }

    // ---- epilogue: scatter-add via vector reds ----
    const int q = lane & 3;
    #pragma unroll
    for (int e = 0; e < 2; e++) {
        const int el = eoff + 8 * e;
        const int eg = e_base + el;
        if (eg >= E) continue;
        float* op = out + (size_t)dsts[el] * 64;
        const float k0 = attr[el * 4 + 1];
        const float k1 = attr[el * 4 + 2];
        const float k2 = attr[el * 4 + 3];

        #pragma unroll
        for (int p = 0; p < 2; p++) {
            float m0a, m0b, ta, tb;
            float a0a, a0b, a1a, a1b, a2a, a2b;
            unpack2(acc[0][e][p], m0a, m0b);
            unpack2(acc[1][e][p], ta, tb);
            unpack2(acc[2][e][p], a0a, a0b);
            unpack2(acc[3][e][p], a1a, a1b);
            unpack2(acc[4][e][p], a2a, a2b);
            const int v = 8 * p + 2 * q;
            red2(op + v, SCALE_OUT * m0a, SCALE_OUT * m0b);
            const int base = 16 + 3 * v;
            red2(op + base,     SCALE_OUT * fmaf(k0, ta, a0a), SCALE_OUT * fmaf(k1, ta, a1a));
            red2(op + base + 2, SCALE_OUT * fmaf(k2, ta, a2a), SCALE_OUT * fmaf(k0, tb, a0b));
            red2(op + base + 4, SCALE_OUT * fmaf(k1, tb, a1b), SCALE_OUT * fmaf(k2, tb, a2b));
        }
    }
}

extern "C" void kernel_launch(void* const* d_in, const int* in_sizes, int n_in,
                              void* d_out, int out_size)
{
    const float* x         = (const float*)d_in[0];
    const float* edge_attr = (const float*)d_in[1];
    const float* edge_len  = (const float*)d_in[2];
    const int*   src       = (const int*)d_in[3];
    const int*   dst       = (const int*)d_in[4];
    const float* W1        = (const float*)d_in[5];
    const float* W2        = (const float*)d_in[6];
    const float* L0        = (const float*)d_in[7];
    const float* L1        = (const float*)d_in[8];
    float* out = (float*)d_out;

    const int E = in_sizes[2];
    const int Nnodes = in_sizes[0] / 64;

    cudaFuncSetAttribute(edge_mma_kernel, cudaFuncAttributeMaxDynamicSharedMemorySize, SMEM_BYTES);

    const int sc_blocks = (Nnodes + 255) / 256;
    pre_kernel<<<PREP_BLOCKS + sc_blocks, 256>>>(W2, x, L0, L1, out, Nnodes);
    edge_mma_kernel<<<(E + TILE_E - 1) / TILE_E, THREADS, SMEM_BYTES>>>(
        x, edge_attr, edge_len, src, dst, W1, out, E);
}